// round 2
// baseline (speedup 1.0000x reference)
#include <cuda_runtime.h>
#include <math.h>

#define NB   16384
#define HH   512
#define NOUT 4
#define NFF  2048
#define NHOR 5

// ---------------- scratch (static device globals; no allocations) -----------
__device__ float g_gh[(size_t)NB * 3 * HH];    // GRU gate pre-activations [B,3H]
__device__ float g_hcat[(size_t)NB * 2 * HH];  // [h1 | h2]  [B,2H]
__device__ float g_hx[(size_t)NB * HH];        // hx         [B,H]
__device__ float g_xy[(size_t)NB * NOUT];      // running xy [B,4]
__device__ float g_t[(size_t)NB * NFF];        // MLP hidden [B,FF]

// ---------------- packed f32x2 helpers (sm_103a FFMA2 pipe) ------------------
__device__ __forceinline__ unsigned long long pack2f(float lo, float hi) {
    unsigned long long r;
    asm("mov.b64 %0, {%1, %2};" : "=l"(r) : "f"(lo), "f"(hi));
    return r;
}
__device__ __forceinline__ unsigned long long ffma2(unsigned long long a,
                                                    unsigned long long b,
                                                    unsigned long long c) {
    unsigned long long d;
    asm("fma.rn.f32x2 %0, %1, %2, %3;" : "=l"(d) : "l"(a), "l"(b), "l"(c));
    return d;
}
__device__ __forceinline__ void unpack2f(unsigned long long v, float& lo, float& hi) {
    asm("mov.b64 {%0, %1}, %2;" : "=f"(lo), "=f"(hi) : "l"(v));
}

// ---------------- generic C[B,N] = act(actA(A[B,K]) @ W[N,K]^T + bias) -------
// BM=128, BN=128, BK=16, 256 threads, 8x8 per-thread tile via 32 ffma2 accs.
template <int RELU_A, int RELU_C>
__global__ __launch_bounds__(256, 2)
void gemm_bias_kernel(const float* __restrict__ A, int lda,
                      const float* __restrict__ W, int K,
                      const float* __restrict__ bias,
                      float* __restrict__ C, int N)
{
    __shared__ float As[16][132];
    __shared__ float Ws[16][132];

    const int tid = threadIdx.x;
    const int bn = blockIdx.x, bm = blockIdx.y;
    const int tx = tid & 15, ty = tid >> 4;
    const int m0 = ty * 8, n0 = tx * 8;

    const float* Ab = A + (size_t)bm * 128 * lda;
    const float* Wb = W + (size_t)bn * 128 * K;

    const int lrow = tid >> 2;        // 0..63
    const int lcol = (tid & 3) * 4;   // 0,4,8,12

    unsigned long long acc[8][4];     // [n][m-pair], pair = (m even, m odd)
#pragma unroll
    for (int i = 0; i < 8; ++i)
#pragma unroll
        for (int j = 0; j < 4; ++j) acc[i][j] = 0ull;

    float4 pa[2], pw[2];
#pragma unroll
    for (int h = 0; h < 2; ++h) {
        pa[h] = *(const float4*)(Ab + (size_t)(lrow + 64 * h) * lda + lcol);
        pw[h] = *(const float4*)(Wb + (size_t)(lrow + 64 * h) * K + lcol);
    }

    const int T = K >> 4;
    for (int t = 0; t < T; ++t) {
        // commit prefetched tile to smem (transposed to [k][m] / [k][n])
#pragma unroll
        for (int h = 0; h < 2; ++h) {
            float4 v = pa[h];
            if (RELU_A) {
                v.x = fmaxf(v.x, 0.f); v.y = fmaxf(v.y, 0.f);
                v.z = fmaxf(v.z, 0.f); v.w = fmaxf(v.w, 0.f);
            }
            int r = lrow + 64 * h;
            As[lcol + 0][r] = v.x; As[lcol + 1][r] = v.y;
            As[lcol + 2][r] = v.z; As[lcol + 3][r] = v.w;
            float4 w = pw[h];
            Ws[lcol + 0][r] = w.x; Ws[lcol + 1][r] = w.y;
            Ws[lcol + 2][r] = w.z; Ws[lcol + 3][r] = w.w;
        }
        __syncthreads();
        if (t + 1 < T) {
            int kp = (t + 1) * 16 + lcol;
#pragma unroll
            for (int h = 0; h < 2; ++h) {
                pa[h] = *(const float4*)(Ab + (size_t)(lrow + 64 * h) * lda + kp);
                pw[h] = *(const float4*)(Wb + (size_t)(lrow + 64 * h) * K + kp);
            }
        }
#pragma unroll
        for (int kk = 0; kk < 16; ++kk) {
            float4 a0 = *(const float4*)&As[kk][m0];
            float4 a1 = *(const float4*)&As[kk][m0 + 4];
            float4 b0 = *(const float4*)&Ws[kk][n0];
            float4 b1 = *(const float4*)&Ws[kk][n0 + 4];
            unsigned long long a2[4];
            a2[0] = pack2f(a0.x, a0.y); a2[1] = pack2f(a0.z, a0.w);
            a2[2] = pack2f(a1.x, a1.y); a2[3] = pack2f(a1.z, a1.w);
            float bv[8] = {b0.x, b0.y, b0.z, b0.w, b1.x, b1.y, b1.z, b1.w};
#pragma unroll
            for (int nj = 0; nj < 8; ++nj) {
                unsigned long long b2 = pack2f(bv[nj], bv[nj]);
#pragma unroll
                for (int mp = 0; mp < 4; ++mp)
                    acc[nj][mp] = ffma2(a2[mp], b2, acc[nj][mp]);
            }
        }
        __syncthreads();
    }

    float cc[8][8];  // [local row][local col]
#pragma unroll
    for (int nj = 0; nj < 8; ++nj)
#pragma unroll
        for (int mp = 0; mp < 4; ++mp)
            unpack2f(acc[nj][mp], cc[2 * mp][nj], cc[2 * mp + 1][nj]);

    float bb[8];
#pragma unroll
    for (int nj = 0; nj < 8; ++nj) bb[nj] = bias[bn * 128 + n0 + nj];

#pragma unroll
    for (int p = 0; p < 8; ++p) {
        int row = bm * 128 + m0 + p;
        float* cp = C + (size_t)row * N + bn * 128 + n0;
        float4 v0, v1;
        v0.x = cc[p][0] + bb[0]; v0.y = cc[p][1] + bb[1];
        v0.z = cc[p][2] + bb[2]; v0.w = cc[p][3] + bb[3];
        v1.x = cc[p][4] + bb[4]; v1.y = cc[p][5] + bb[5];
        v1.z = cc[p][6] + bb[6]; v1.w = cc[p][7] + bb[7];
        if (RELU_C) {
            v0.x = fmaxf(v0.x, 0.f); v0.y = fmaxf(v0.y, 0.f);
            v0.z = fmaxf(v0.z, 0.f); v0.w = fmaxf(v0.w, 0.f);
            v1.x = fmaxf(v1.x, 0.f); v1.y = fmaxf(v1.y, 0.f);
            v1.z = fmaxf(v1.z, 0.f); v1.w = fmaxf(v1.w, 0.f);
        }
        *(float4*)cp = v0;
        *(float4*)(cp + 4) = v1;
    }
}

// ---------------- GRU gate fusion (r,z,n order; PyTorch semantics) -----------
// gh already contains h @ w_hh^T + b_hh. x contributes via tiny K=4 dot here.
__global__ void gru_gates_kernel(const float* __restrict__ gh,
                                 const float* __restrict__ x, int ldx,
                                 const float* __restrict__ hprev, int ldh,
                                 const float* __restrict__ w_ih,   // [3H,4]
                                 const float* __restrict__ b_ih,   // [3H]
                                 float* __restrict__ hout, int ldo)
{
    int j = blockIdx.x * blockDim.x + threadIdx.x;   // 0..H-1
    int b = blockIdx.y;
    float4 xv = *(const float4*)(x + (size_t)b * ldx);

    float ig[3];
#pragma unroll
    for (int g = 0; g < 3; ++g) {
        int r = g * HH + j;
        float4 w = *(const float4*)(w_ih + (size_t)r * 4);
        ig[g] = b_ih[r] + xv.x * w.x + xv.y * w.y + xv.z * w.z + xv.w * w.w;
    }
    const float* ghb = gh + (size_t)b * (3 * HH);
    float gr = ghb[j], gz = ghb[HH + j], gn = ghb[2 * HH + j];
    float r = 1.f / (1.f + expf(-(ig[0] + gr)));
    float z = 1.f / (1.f + expf(-(ig[1] + gz)));
    float n = tanhf(ig[2] + r * gn);
    float hp = hprev[(size_t)b * ldh + j];
    hout[(size_t)b * ldo + j] = (1.f - z) * n + z * hp;
}

// ---------------- MLP layer 2 (FF->4), xy accumulate, output write ----------
__global__ void mlp2_kernel(const float* __restrict__ t,   // [B,FF]
                            const float* __restrict__ w2,  // [4,FF]
                            const float* __restrict__ b2,  // [4]
                            float* __restrict__ xy,        // [B,4]
                            float* __restrict__ out,       // [B,HOR,4]
                            int step)
{
    int warp = (blockIdx.x * blockDim.x + threadIdx.x) >> 5;
    int lane = threadIdx.x & 31;
    if (warp >= NB) return;
    const float* tr = t + (size_t)warp * NFF;
    float s0 = 0.f, s1 = 0.f, s2 = 0.f, s3 = 0.f;
    for (int k = lane * 4; k < NFF; k += 128) {
        float4 tv = *(const float4*)(tr + k);
        float4 wa = *(const float4*)(w2 + 0 * NFF + k);
        float4 wb = *(const float4*)(w2 + 1 * NFF + k);
        float4 wc = *(const float4*)(w2 + 2 * NFF + k);
        float4 wd = *(const float4*)(w2 + 3 * NFF + k);
        s0 += tv.x * wa.x + tv.y * wa.y + tv.z * wa.z + tv.w * wa.w;
        s1 += tv.x * wb.x + tv.y * wb.y + tv.z * wb.z + tv.w * wb.w;
        s2 += tv.x * wc.x + tv.y * wc.y + tv.z * wc.z + tv.w * wc.w;
        s3 += tv.x * wd.x + tv.y * wd.y + tv.z * wd.z + tv.w * wd.w;
    }
#pragma unroll
    for (int off = 16; off > 0; off >>= 1) {
        s0 += __shfl_xor_sync(0xffffffffu, s0, off);
        s1 += __shfl_xor_sync(0xffffffffu, s1, off);
        s2 += __shfl_xor_sync(0xffffffffu, s2, off);
        s3 += __shfl_xor_sync(0xffffffffu, s3, off);
    }
    if (lane == 0) {
        float4 cur = *(float4*)(xy + (size_t)warp * 4);
        cur.x += s0 + b2[0];
        cur.y += s1 + b2[1];
        cur.z += s2 + b2[2];
        cur.w += s3 + b2[3];
        *(float4*)(xy + (size_t)warp * 4) = cur;
        *(float4*)(out + (size_t)warp * NHOR * NOUT + step * NOUT) = cur;
    }
}

__global__ void zero_kernel(float* __restrict__ p, int n)
{
    int i = blockIdx.x * blockDim.x + threadIdx.x;
    if (i < n) p[i] = 0.f;
}

// ---------------- launch --------------------------------------------------
extern "C" void kernel_launch(void* const* d_in, const int* in_sizes, int n_in,
                              void* d_out, int out_size)
{
    const float* pv   = (const float*)d_in[0];
    const float* ptf  = (const float*)d_in[1];
    const float* w_ih = (const float*)d_in[2];
    const float* w_hh = (const float*)d_in[3];
    const float* b_ih = (const float*)d_in[4];
    const float* b_hh = (const float*)d_in[5];
    const float* w_fc = (const float*)d_in[6];
    const float* b_fc = (const float*)d_in[7];
    const float* w1   = (const float*)d_in[8];
    const float* b1   = (const float*)d_in[9];
    const float* w2   = (const float*)d_in[10];
    const float* b2   = (const float*)d_in[11];
    float* out = (float*)d_out;

    float *gh, *hcat, *hx, *xy, *tt;
    cudaGetSymbolAddress((void**)&gh,   g_gh);
    cudaGetSymbolAddress((void**)&hcat, g_hcat);
    cudaGetSymbolAddress((void**)&hx,   g_hx);
    cudaGetSymbolAddress((void**)&xy,   g_xy);
    cudaGetSymbolAddress((void**)&tt,   g_t);

    zero_kernel<<<(NB * NOUT) / 256, 256>>>(xy, NB * NOUT);

    const float* hprev = ptf;                 // [B,H], lda = H
    for (int i = 0; i < NHOR; ++i) {
        // cell 1: gh = hprev @ w_hh^T + b_hh ; h1 = gates(xy, gh, hprev)
        gemm_bias_kernel<0, 0><<<dim3(3 * HH / 128, NB / 128), 256>>>(
            hprev, HH, w_hh, HH, b_hh, gh, 3 * HH);
        gru_gates_kernel<<<dim3(HH / 256, NB), 256>>>(
            gh, xy, NOUT, hprev, HH, w_ih, b_ih, hcat, 2 * HH);

        // cell 2: gh = h1 @ w_hh^T + b_hh ; h2 = gates(pv_i, gh, h1)
        gemm_bias_kernel<0, 0><<<dim3(3 * HH / 128, NB / 128), 256>>>(
            hcat, 2 * HH, w_hh, HH, b_hh, gh, 3 * HH);
        gru_gates_kernel<<<dim3(HH / 256, NB), 256>>>(
            gh, pv + i * NOUT, NHOR * NOUT, hcat, 2 * HH, w_ih, b_ih,
            hcat + HH, 2 * HH);

        // hx = [h1|h2] @ w_fc^T + b_fc
        gemm_bias_kernel<0, 0><<<dim3(HH / 128, NB / 128), 256>>>(
            hcat, 2 * HH, w_fc, 2 * HH, b_fc, hx, HH);

        // t = relu(relu(hx) @ w1^T + b1)
        gemm_bias_kernel<1, 1><<<dim3(NFF / 128, NB / 128), 256>>>(
            hx, HH, w1, HH, b1, tt, NFF);

        // xy += t @ w2^T + b2 ; out[:, i, :] = xy
        mlp2_kernel<<<(NB * 32) / 256, 256>>>(tt, w2, b2, xy, out, i);

        hprev = hx;
    }
}

// round 6
// speedup vs baseline: 1.7068x; 1.7068x over previous
#include <cuda_runtime.h>
#include <cuda_bf16.h>
#include <math.h>
#include <stdint.h>

#define NB   16384
#define HH   512
#define NOUT 4
#define NFF  2048
#define NHOR 5

// ---------------- scratch (static device globals; no allocations) -----------
__device__ float g_gh[(size_t)NB * 3 * HH];    // GRU gate pre-activations [B,3H]
__device__ float g_hcat[(size_t)NB * 2 * HH];  // [h1 | h2]  [B,2H]
__device__ float g_hx[(size_t)NB * HH];        // hx         [B,H]
__device__ float g_xy[(size_t)NB * NOUT];      // running xy [B,4]
__device__ float g_t[(size_t)NB * NFF];        // MLP hidden [B,FF]

// ---------------- helpers ---------------------------------------------------
__device__ __forceinline__ uint32_t smem_u32(const void* p) {
    uint32_t a;
    asm("{ .reg .u64 t; cvta.to.shared.u64 t, %1; cvt.u32.u64 %0, t; }"
        : "=r"(a) : "l"(p));
    return a;
}

// split one float pair into bf16 hi + bf16(lo residual), packed as b16x2
__device__ __forceinline__ void split2(float x, float y, uint32_t& hi, uint32_t& lo) {
    __nv_bfloat16 hx = __float2bfloat16(x);
    __nv_bfloat16 hy = __float2bfloat16(y);
    float rx = x - __bfloat162float(hx);
    float ry = y - __bfloat162float(hy);
    __nv_bfloat162 hp; hp.x = hx; hp.y = hy;
    __nv_bfloat162 lp; lp.x = __float2bfloat16(rx); lp.y = __float2bfloat16(ry);
    hi = *reinterpret_cast<uint32_t*>(&hp);
    lo = *reinterpret_cast<uint32_t*>(&lp);
}

__device__ __forceinline__ void ldsm4(uint32_t& r0, uint32_t& r1,
                                      uint32_t& r2, uint32_t& r3, uint32_t addr) {
    asm volatile("ldmatrix.sync.aligned.m8n8.x4.shared.b16 {%0,%1,%2,%3}, [%4];"
                 : "=r"(r0), "=r"(r1), "=r"(r2), "=r"(r3) : "r"(addr));
}
__device__ __forceinline__ void hmma(float* d, const uint32_t* a,
                                     uint32_t b0, uint32_t b1) {
    asm volatile(
        "mma.sync.aligned.m16n8k16.row.col.f32.bf16.bf16.f32 "
        "{%0,%1,%2,%3}, {%4,%5,%6,%7}, {%8,%9}, {%0,%1,%2,%3};"
        : "+f"(d[0]), "+f"(d[1]), "+f"(d[2]), "+f"(d[3])
        : "r"(a[0]), "r"(a[1]), "r"(a[2]), "r"(a[3]), "r"(b0), "r"(b1));
}

// smem plane geometry: 128 rows x 64 bf16, row stride padded to 144 bytes
#define ROWB   144
#define PLANE  (128 * ROWB)            // 18432 B
#define SMEM_DYN (4 * PLANE + 64)      // Ah, Al, Wh, Wl

// =====================  HMMA split-bf16 GEMM  ===============================
// C[B,N] = act( actA(A[B,K]) @ W[N,K]^T + bias ), fp32 in/out, ~fp32 accuracy.
// 128x128 tile, 8 warps (2x4), warp tile 64x32, K-chunk 64, 3 precision passes.
template <int RELU_A, int RELU_C>
__global__ __launch_bounds__(256, 2)
void hmma_gemm(const float* __restrict__ A, int lda,
               const float* __restrict__ W, int K,
               const float* __restrict__ bias,
               float* __restrict__ C, int N)
{
    extern __shared__ char dsm[];
    char* pAh = dsm;
    char* pAl = dsm + PLANE;
    char* pWh = dsm + 2 * PLANE;
    char* pWl = dsm + 3 * PLANE;
    const uint32_t sb  = smem_u32(dsm);
    const uint32_t sAh = sb, sAl = sb + PLANE, sWh = sb + 2 * PLANE, sWl = sb + 3 * PLANE;

    const int tid  = threadIdx.x;
    const int wid  = tid >> 5;
    const int lane = tid & 31;
    const int wm   = wid & 1;        // 0..1 -> 64-row band
    const int wn   = wid >> 1;       // 0..3 -> 32-col band
    const int grp  = lane >> 3;
    const int wi   = lane & 7;

    // ldmatrix per-lane byte offsets (within a plane)
    const uint32_t aoff = (uint32_t)(wm * 64 + (grp & 1) * 8 + wi) * ROWB
                        + (uint32_t)((grp >> 1) * 8) * 2;
    const uint32_t woff = (uint32_t)(wn * 32 + (grp >> 1) * 8 + wi) * ROWB
                        + (uint32_t)((grp & 1) * 8) * 2;

    const float* Ab = A + (size_t)blockIdx.y * 128 * lda;
    const float* Wb = W + (size_t)blockIdx.x * 128 * K;

    float acc[4][4][4];
#pragma unroll
    for (int mt = 0; mt < 4; ++mt)
#pragma unroll
        for (int nt = 0; nt < 4; ++nt)
#pragma unroll
            for (int r = 0; r < 4; ++r) acc[mt][nt][r] = 0.f;

    const int nchunk = K >> 6;
    for (int c = 0; c < nchunk; ++c) {
        const int k0 = c << 6;
        // ---- fill A planes (split fp32 -> bf16 hi/lo) ----
#pragma unroll
        for (int it = 0; it < 8; ++it) {
            int e = (it * 256 + tid) * 4;          // element idx in 128x64 tile
            int r = e >> 6, col = e & 63;
            float4 v = *(const float4*)(Ab + (size_t)r * lda + k0 + col);
            if (RELU_A) {
                v.x = fmaxf(v.x, 0.f); v.y = fmaxf(v.y, 0.f);
                v.z = fmaxf(v.z, 0.f); v.w = fmaxf(v.w, 0.f);
            }
            uint32_t h0, l0, h1, l1;
            split2(v.x, v.y, h0, l0);
            split2(v.z, v.w, h1, l1);
            uint32_t boff = r * ROWB + col * 2;
            *(uint2*)(pAh + boff) = make_uint2(h0, h1);
            *(uint2*)(pAl + boff) = make_uint2(l0, l1);
        }
        // ---- fill W planes ----
#pragma unroll
        for (int it = 0; it < 8; ++it) {
            int e = (it * 256 + tid) * 4;
            int r = e >> 6, col = e & 63;
            float4 v = *(const float4*)(Wb + (size_t)r * K + k0 + col);
            uint32_t h0, l0, h1, l1;
            split2(v.x, v.y, h0, l0);
            split2(v.z, v.w, h1, l1);
            uint32_t boff = r * ROWB + col * 2;
            *(uint2*)(pWh + boff) = make_uint2(h0, h1);
            *(uint2*)(pWl + boff) = make_uint2(l0, l1);
        }
        __syncthreads();

        // ---- 3 passes: hi*hi, lo*hi, hi*lo ----
#pragma unroll
        for (int pass = 0; pass < 3; ++pass) {
            const uint32_t pa = (pass == 1) ? sAl : sAh;
            const uint32_t pw = (pass == 2) ? sWl : sWh;
#pragma unroll
            for (int ks = 0; ks < 4; ++ks) {
                const uint32_t kb = (uint32_t)(ks * 16) * 2;   // byte offset in k
                uint32_t a[4][4];
#pragma unroll
                for (int mt = 0; mt < 4; ++mt)
                    ldsm4(a[mt][0], a[mt][1], a[mt][2], a[mt][3],
                          pa + aoff + (uint32_t)(mt * 16) * ROWB + kb);
                uint32_t b[4][2];
#pragma unroll
                for (int nh = 0; nh < 2; ++nh) {
                    uint32_t r0, r1, r2, r3;
                    ldsm4(r0, r1, r2, r3,
                          pw + woff + (uint32_t)(nh * 16) * ROWB + kb);
                    b[nh * 2 + 0][0] = r0; b[nh * 2 + 0][1] = r1;
                    b[nh * 2 + 1][0] = r2; b[nh * 2 + 1][1] = r3;
                }
#pragma unroll
                for (int mt = 0; mt < 4; ++mt)
#pragma unroll
                    for (int nt = 0; nt < 4; ++nt)
                        hmma(acc[mt][nt], a[mt], b[nt][0], b[nt][1]);
            }
        }
        __syncthreads();
    }

    // ---- epilogue: bias (+ReLU) + fp32 store --------------------------------
    const int row0 = blockIdx.y * 128 + wm * 64 + (lane >> 2);
    const int col0 = blockIdx.x * 128 + wn * 32 + (lane & 3) * 2;
#pragma unroll
    for (int mt = 0; mt < 4; ++mt) {
#pragma unroll
        for (int nt = 0; nt < 4; ++nt) {
            int cI = col0 + nt * 8;
            float b0 = bias[cI], b1 = bias[cI + 1];
            float2 v0, v1;
            v0.x = acc[mt][nt][0] + b0; v0.y = acc[mt][nt][1] + b1;
            v1.x = acc[mt][nt][2] + b0; v1.y = acc[mt][nt][3] + b1;
            if (RELU_C) {
                v0.x = fmaxf(v0.x, 0.f); v0.y = fmaxf(v0.y, 0.f);
                v1.x = fmaxf(v1.x, 0.f); v1.y = fmaxf(v1.y, 0.f);
            }
            int r = row0 + mt * 16;
            *(float2*)(C + (size_t)r * N + cI)       = v0;
            *(float2*)(C + (size_t)(r + 8) * N + cI) = v1;
        }
    }
}

// ---------------- GRU gate fusion (r,z,n order; PyTorch semantics) -----------
__global__ void gru_gates_kernel(const float* __restrict__ gh,
                                 const float* __restrict__ x, int ldx,
                                 const float* __restrict__ hprev, int ldh,
                                 const float* __restrict__ w_ih,   // [3H,4]
                                 const float* __restrict__ b_ih,   // [3H]
                                 float* __restrict__ hout, int ldo)
{
    int j = blockIdx.x * blockDim.x + threadIdx.x;   // 0..H-1
    int b = blockIdx.y;
    float4 xv = *(const float4*)(x + (size_t)b * ldx);

    float ig[3];
#pragma unroll
    for (int g = 0; g < 3; ++g) {
        int r = g * HH + j;
        float4 w = *(const float4*)(w_ih + (size_t)r * 4);
        ig[g] = b_ih[r] + xv.x * w.x + xv.y * w.y + xv.z * w.z + xv.w * w.w;
    }
    const float* ghb = gh + (size_t)b * (3 * HH);
    float gr = ghb[j], gz = ghb[HH + j], gn = ghb[2 * HH + j];
    float r = 1.f / (1.f + expf(-(ig[0] + gr)));
    float z = 1.f / (1.f + expf(-(ig[1] + gz)));
    float n = tanhf(ig[2] + r * gn);
    float hp = hprev[(size_t)b * ldh + j];
    hout[(size_t)b * ldo + j] = (1.f - z) * n + z * hp;
}

// ---------------- MLP layer 2 (FF->4), xy accumulate, output write ----------
__global__ void mlp2_kernel(const float* __restrict__ t,   // [B,FF]
                            const float* __restrict__ w2,  // [4,FF]
                            const float* __restrict__ b2,  // [4]
                            float* __restrict__ xy,        // [B,4]
                            float* __restrict__ out,       // [B,HOR,4]
                            int step)
{
    int warp = (blockIdx.x * blockDim.x + threadIdx.x) >> 5;
    int lane = threadIdx.x & 31;
    if (warp >= NB) return;
    const float* tr = t + (size_t)warp * NFF;
    float s0 = 0.f, s1 = 0.f, s2 = 0.f, s3 = 0.f;
    for (int k = lane * 4; k < NFF; k += 128) {
        float4 tv = *(const float4*)(tr + k);
        float4 wa = *(const float4*)(w2 + 0 * NFF + k);
        float4 wb = *(const float4*)(w2 + 1 * NFF + k);
        float4 wc = *(const float4*)(w2 + 2 * NFF + k);
        float4 wd = *(const float4*)(w2 + 3 * NFF + k);
        s0 += tv.x * wa.x + tv.y * wa.y + tv.z * wa.z + tv.w * wa.w;
        s1 += tv.x * wb.x + tv.y * wb.y + tv.z * wb.z + tv.w * wb.w;
        s2 += tv.x * wc.x + tv.y * wc.y + tv.z * wc.z + tv.w * wc.w;
        s3 += tv.x * wd.x + tv.y * wd.y + tv.z * wd.z + tv.w * wd.w;
    }
#pragma unroll
    for (int off = 16; off > 0; off >>= 1) {
        s0 += __shfl_xor_sync(0xffffffffu, s0, off);
        s1 += __shfl_xor_sync(0xffffffffu, s1, off);
        s2 += __shfl_xor_sync(0xffffffffu, s2, off);
        s3 += __shfl_xor_sync(0xffffffffu, s3, off);
    }
    if (lane == 0) {
        float4 cur = *(float4*)(xy + (size_t)warp * 4);
        cur.x += s0 + b2[0];
        cur.y += s1 + b2[1];
        cur.z += s2 + b2[2];
        cur.w += s3 + b2[3];
        *(float4*)(xy + (size_t)warp * 4) = cur;
        *(float4*)(out + (size_t)warp * NHOR * NOUT + step * NOUT) = cur;
    }
}

__global__ void zero_kernel(float* __restrict__ p, int n)
{
    int i = blockIdx.x * blockDim.x + threadIdx.x;
    if (i < n) p[i] = 0.f;
}

// ---------------- launch --------------------------------------------------
extern "C" void kernel_launch(void* const* d_in, const int* in_sizes, int n_in,
                              void* d_out, int out_size)
{
    const float* pv   = (const float*)d_in[0];
    const float* ptf  = (const float*)d_in[1];
    const float* w_ih = (const float*)d_in[2];
    const float* w_hh = (const float*)d_in[3];
    const float* b_ih = (const float*)d_in[4];
    const float* b_hh = (const float*)d_in[5];
    const float* w_fc = (const float*)d_in[6];
    const float* b_fc = (const float*)d_in[7];
    const float* w1   = (const float*)d_in[8];
    const float* b1   = (const float*)d_in[9];
    const float* w2   = (const float*)d_in[10];
    const float* b2   = (const float*)d_in[11];
    float* out = (float*)d_out;

    float *gh, *hcat, *hx, *xy, *tt;
    cudaGetSymbolAddress((void**)&gh,   g_gh);
    cudaGetSymbolAddress((void**)&hcat, g_hcat);
    cudaGetSymbolAddress((void**)&hx,   g_hx);
    cudaGetSymbolAddress((void**)&xy,   g_xy);
    cudaGetSymbolAddress((void**)&tt,   g_t);

    cudaFuncSetAttribute(hmma_gemm<0, 0>, cudaFuncAttributeMaxDynamicSharedMemorySize, SMEM_DYN);
    cudaFuncSetAttribute(hmma_gemm<1, 1>, cudaFuncAttributeMaxDynamicSharedMemorySize, SMEM_DYN);

    zero_kernel<<<(NB * NOUT) / 256, 256>>>(xy, NB * NOUT);

    const float* hprev = ptf;                 // [B,H], lda = H
    for (int i = 0; i < NHOR; ++i) {
        // cell 1: gh = hprev @ w_hh^T + b_hh ; h1 = gates(xy, gh, hprev)
        hmma_gemm<0, 0><<<dim3(3 * HH / 128, NB / 128), 256, SMEM_DYN>>>(
            hprev, (i == 0) ? HH : HH, w_hh, HH, b_hh, gh, 3 * HH);
        gru_gates_kernel<<<dim3(HH / 256, NB), 256>>>(
            gh, xy, NOUT, hprev, HH, w_ih, b_ih, hcat, 2 * HH);

        // cell 2: gh = h1 @ w_hh^T + b_hh ; h2 = gates(pv_i, gh, h1)
        hmma_gemm<0, 0><<<dim3(3 * HH / 128, NB / 128), 256, SMEM_DYN>>>(
            hcat, 2 * HH, w_hh, HH, b_hh, gh, 3 * HH);
        gru_gates_kernel<<<dim3(HH / 256, NB), 256>>>(
            gh, pv + i * NOUT, NHOR * NOUT, hcat, 2 * HH, w_ih, b_ih,
            hcat + HH, 2 * HH);

        // hx = [h1|h2] @ w_fc^T + b_fc
        hmma_gemm<0, 0><<<dim3(HH / 128, NB / 128), 256, SMEM_DYN>>>(
            hcat, 2 * HH, w_fc, 2 * HH, b_fc, hx, HH);

        // t = relu(relu(hx) @ w1^T + b1)
        hmma_gemm<1, 1><<<dim3(NFF / 128, NB / 128), 256, SMEM_DYN>>>(
            hx, HH, w1, HH, b1, tt, NFF);

        // xy += t @ w2^T + b2 ; out[:, i, :] = xy
        mlp2_kernel<<<(NB * 32) / 256, 256>>>(tt, w2, b2, xy, out, i);

        hprev = hx;
    }
}

// round 7
// speedup vs baseline: 2.5391x; 1.4877x over previous
#include <cuda_runtime.h>
#include <cuda_fp16.h>
#include <math.h>
#include <stdint.h>

#define NB   16384
#define HH   512
#define NOUT 4
#define NFF  2048
#define NHOR 5

// ---------------- fp32 scratch ----------------------------------------------
__device__ float g_gh[(size_t)NB * 3 * HH];   // gate pre-activations [B,3H]
__device__ float g_hx[(size_t)NB * HH];       // hx fp32 (gates hprev)
__device__ float g_h1[(size_t)NB * HH];       // h1 fp32 (cell-2 gates hprev)
__device__ float g_xy[(size_t)NB * NOUT];     // running xy
__device__ float g_t[(size_t)NB * NFF];       // MLP hidden

// ---------------- fp16 hi/lo planes (GEMM operands) -------------------------
__device__ __align__(16) __half g_hp_h[(size_t)NB * HH];      // hprev
__device__ __align__(16) __half g_hp_l[(size_t)NB * HH];
__device__ __align__(16) __half g_hc_h[(size_t)NB * 2 * HH];  // hcat [h1|h2]
__device__ __align__(16) __half g_hc_l[(size_t)NB * 2 * HH];
__device__ __align__(16) __half g_hr_h[(size_t)NB * HH];      // relu(hx)
__device__ __align__(16) __half g_hr_l[(size_t)NB * HH];
__device__ __align__(16) __half g_whh_h[3 * HH * HH];
__device__ __align__(16) __half g_whh_l[3 * HH * HH];
__device__ __align__(16) __half g_wfc_h[HH * 2 * HH];
__device__ __align__(16) __half g_wfc_l[HH * 2 * HH];
__device__ __align__(16) __half g_w1_h[NFF * HH];
__device__ __align__(16) __half g_w1_l[NFF * HH];

// ---------------- helpers ---------------------------------------------------
__device__ __forceinline__ uint32_t smem_u32(const void* p) {
    uint32_t a;
    asm("{ .reg .u64 t; cvta.to.shared.u64 t, %1; cvt.u32.u64 %0, t; }"
        : "=r"(a) : "l"(p));
    return a;
}
__device__ __forceinline__ void split1(float x, __half& h, __half& l) {
    h = __float2half_rn(x);
    l = __float2half_rn(x - __half2float(h));
}
__device__ __forceinline__ void ldsm4(uint32_t& r0, uint32_t& r1,
                                      uint32_t& r2, uint32_t& r3, uint32_t addr) {
    asm volatile("ldmatrix.sync.aligned.m8n8.x4.shared.b16 {%0,%1,%2,%3}, [%4];"
                 : "=r"(r0), "=r"(r1), "=r"(r2), "=r"(r3) : "r"(addr));
}
__device__ __forceinline__ void hmma(float* d, const uint32_t* a,
                                     uint32_t b0, uint32_t b1) {
    asm volatile(
        "mma.sync.aligned.m16n8k16.row.col.f32.f16.f16.f32 "
        "{%0,%1,%2,%3}, {%4,%5,%6,%7}, {%8,%9}, {%0,%1,%2,%3};"
        : "+f"(d[0]), "+f"(d[1]), "+f"(d[2]), "+f"(d[3])
        : "r"(a[0]), "r"(a[1]), "r"(a[2]), "r"(a[3]), "r"(b0), "r"(b1));
}
__device__ __forceinline__ void cpasync16(uint32_t dst, const void* src) {
    asm volatile("cp.async.cg.shared.global [%0], [%1], 16;" :: "r"(dst), "l"(src));
}

// smem plane: 128 rows x 32 fp16 = 64B/row; XOR swizzle keeps LDGSTS stores and
// ldmatrix reads conflict-free without padding.
#define BK      32
#define STAGES  3
#define PL      8192            // one plane: 128*64B
#define STG     (4 * PL)        // Ah, Al, Wh, Wl
#define SMEM_DYN (STAGES * STG) // 96 KB

__device__ __forceinline__ uint32_t sw_addr(uint32_t base, int row, int cgrp) {
    return base + row * 64 + (uint32_t)((cgrp ^ ((row >> 1) & 3)) << 4);
}

// =====================  split-fp16 HMMA GEMM, cp.async 3-stage  =============
// C[B,N] = act(A @ W^T + bias); A,W given as fp16 hi/lo planes.
// 128x128 tile, 8 warps (2x4), 3 precision passes sharing one fp32 accumulator.
template <int RELU_C, int WSPLITS>
__global__ __launch_bounds__(256, 2)
void hgemm(const __half* __restrict__ Ah, const __half* __restrict__ Al, int lda,
           const __half* __restrict__ Wh, const __half* __restrict__ Wl, int K,
           const float* __restrict__ bias, float* __restrict__ C, int N,
           __half* __restrict__ Oh, __half* __restrict__ Ol,
           __half* __restrict__ Rh, __half* __restrict__ Rl)
{
    extern __shared__ char dsm[];
    const uint32_t sb = smem_u32(dsm);

    const int tid  = threadIdx.x;
    const int wid  = tid >> 5;
    const int lane = tid & 31;
    const int wm   = wid & 1;
    const int wn   = wid >> 1;
    const int grp  = lane >> 3;
    const int wi   = lane & 7;

    const __half* Abh = Ah + (size_t)blockIdx.y * 128 * lda;
    const __half* Abl = Al + (size_t)blockIdx.y * 128 * lda;
    const __half* Wbh = Wh + (size_t)blockIdx.x * 128 * K;
    const __half* Wbl = Wl + (size_t)blockIdx.x * 128 * K;

    // per-thread copy coords: op o -> row o>>2, 8-col group o&3
    const int r0c = tid >> 2, cg0 = tid & 3;          // ops 0..255
    const int r1c = (tid + 256) >> 2, cg1 = tid & 3;  // ops 256..511

    // per-lane ldmatrix coords
    const int rowA0 = wm * 64 + (grp & 1) * 8 + wi;
    const int sA    = (rowA0 >> 1) & 3;
    const int cA    = grp >> 1;
    const int rowW0 = wn * 32 + (grp >> 1) * 8 + wi;
    const int sW    = (rowW0 >> 1) & 3;
    const int cW    = grp & 1;

    float acc[4][4][4];
#pragma unroll
    for (int mt = 0; mt < 4; ++mt)
#pragma unroll
        for (int nt = 0; nt < 4; ++nt)
#pragma unroll
            for (int r = 0; r < 4; ++r) acc[mt][nt][r] = 0.f;

    const int nchunk = K >> 5;   // K / 32

#define ISSUE(c) do {                                                          \
    int k0_ = (c) << 5;                                                        \
    uint32_t stg_ = sb + (uint32_t)((c) % STAGES) * STG;                       \
    uint32_t d0_ = sw_addr(stg_, r0c, cg0);                                    \
    cpasync16(d0_,          Abh + (size_t)r0c * lda + k0_ + cg0 * 8);          \
    cpasync16(d0_ + PL,     Abl + (size_t)r0c * lda + k0_ + cg0 * 8);          \
    cpasync16(d0_ + 2*PL,   Wbh + (size_t)r0c * K  + k0_ + cg0 * 8);           \
    cpasync16(d0_ + 3*PL,   Wbl + (size_t)r0c * K  + k0_ + cg0 * 8);           \
    uint32_t d1_ = sw_addr(stg_, r1c, cg1);                                    \
    cpasync16(d1_,          Abh + (size_t)r1c * lda + k0_ + cg1 * 8);          \
    cpasync16(d1_ + PL,     Abl + (size_t)r1c * lda + k0_ + cg1 * 8);          \
    cpasync16(d1_ + 2*PL,   Wbh + (size_t)r1c * K  + k0_ + cg1 * 8);           \
    cpasync16(d1_ + 3*PL,   Wbl + (size_t)r1c * K  + k0_ + cg1 * 8);           \
} while (0)

    // prologue: stages 0..STAGES-2
#pragma unroll
    for (int s = 0; s < STAGES - 1; ++s) {
        ISSUE(s);
        asm volatile("cp.async.commit_group;");
    }

    for (int c = 0; c < nchunk; ++c) {
        asm volatile("cp.async.wait_group %0;" :: "n"(STAGES - 2));
        __syncthreads();
        if (c + STAGES - 1 < nchunk) ISSUE(c + STAGES - 1);
        asm volatile("cp.async.commit_group;");

        const uint32_t stg = sb + (uint32_t)(c % STAGES) * STG;
#pragma unroll
        for (int ks = 0; ks < 2; ++ks) {
            uint32_t a[4][4];          // holds A_hi, then reused for A_lo
            uint32_t bh[4][2], bl[4][2];
#pragma unroll
            for (int mt = 0; mt < 4; ++mt) {
                uint32_t ad = stg + (uint32_t)(rowA0 + mt * 16) * 64
                            + (uint32_t)(((ks * 2 + cA) ^ sA) << 4);
                ldsm4(a[mt][0], a[mt][1], a[mt][2], a[mt][3], ad);
            }
#pragma unroll
            for (int nh = 0; nh < 2; ++nh) {
                uint32_t wd = stg + 2 * PL + (uint32_t)(rowW0 + nh * 16) * 64
                            + (uint32_t)(((ks * 2 + cW) ^ sW) << 4);
                uint32_t r0, r1, r2, r3;
                ldsm4(r0, r1, r2, r3, wd);
                bh[nh * 2 + 0][0] = r0; bh[nh * 2 + 0][1] = r1;
                bh[nh * 2 + 1][0] = r2; bh[nh * 2 + 1][1] = r3;
                ldsm4(r0, r1, r2, r3, wd + PL);
                bl[nh * 2 + 0][0] = r0; bl[nh * 2 + 0][1] = r1;
                bl[nh * 2 + 1][0] = r2; bl[nh * 2 + 1][1] = r3;
            }
            // pass 1: A_hi * W_hi ; pass 3: A_hi * W_lo
#pragma unroll
            for (int mt = 0; mt < 4; ++mt)
#pragma unroll
                for (int nt = 0; nt < 4; ++nt) {
                    hmma(acc[mt][nt], a[mt], bh[nt][0], bh[nt][1]);
                    hmma(acc[mt][nt], a[mt], bl[nt][0], bl[nt][1]);
                }
            // pass 2: A_lo * W_hi (reload A planes into same regs)
#pragma unroll
            for (int mt = 0; mt < 4; ++mt) {
                uint32_t ad = stg + PL + (uint32_t)(rowA0 + mt * 16) * 64
                            + (uint32_t)(((ks * 2 + cA) ^ sA) << 4);
                ldsm4(a[mt][0], a[mt][1], a[mt][2], a[mt][3], ad);
            }
#pragma unroll
            for (int mt = 0; mt < 4; ++mt)
#pragma unroll
                for (int nt = 0; nt < 4; ++nt)
                    hmma(acc[mt][nt], a[mt], bh[nt][0], bh[nt][1]);
        }
    }
#undef ISSUE

    // ---- epilogue ----------------------------------------------------------
    const int row0 = blockIdx.y * 128 + wm * 64 + (lane >> 2);
    const int col0 = blockIdx.x * 128 + wn * 32 + (lane & 3) * 2;
#pragma unroll
    for (int mt = 0; mt < 4; ++mt) {
#pragma unroll
        for (int nt = 0; nt < 4; ++nt) {
            const int cI = col0 + nt * 8;
            const float b0 = bias[cI], b1 = bias[cI + 1];
            float2 v0, v1;
            v0.x = acc[mt][nt][0] + b0; v0.y = acc[mt][nt][1] + b1;
            v1.x = acc[mt][nt][2] + b0; v1.y = acc[mt][nt][3] + b1;
            if (RELU_C) {
                v0.x = fmaxf(v0.x, 0.f); v0.y = fmaxf(v0.y, 0.f);
                v1.x = fmaxf(v1.x, 0.f); v1.y = fmaxf(v1.y, 0.f);
            }
            const int r = row0 + mt * 16;
            *(float2*)(C + (size_t)r * N + cI)       = v0;
            *(float2*)(C + (size_t)(r + 8) * N + cI) = v1;
            if (WSPLITS) {
                __half h0, l0, h1, l1;
                // plain split -> Oh/Ol
                split1(v0.x, h0, l0); split1(v0.y, h1, l1);
                *(__half2*)(Oh + (size_t)r * N + cI) = __halves2half2(h0, h1);
                *(__half2*)(Ol + (size_t)r * N + cI) = __halves2half2(l0, l1);
                split1(v1.x, h0, l0); split1(v1.y, h1, l1);
                *(__half2*)(Oh + (size_t)(r + 8) * N + cI) = __halves2half2(h0, h1);
                *(__half2*)(Ol + (size_t)(r + 8) * N + cI) = __halves2half2(l0, l1);
                // relu split -> Rh/Rl
                float r0x = fmaxf(v0.x, 0.f), r0y = fmaxf(v0.y, 0.f);
                float r1x = fmaxf(v1.x, 0.f), r1y = fmaxf(v1.y, 0.f);
                split1(r0x, h0, l0); split1(r0y, h1, l1);
                *(__half2*)(Rh + (size_t)r * N + cI) = __halves2half2(h0, h1);
                *(__half2*)(Rl + (size_t)r * N + cI) = __halves2half2(l0, l1);
                split1(r1x, h0, l0); split1(r1y, h1, l1);
                *(__half2*)(Rh + (size_t)(r + 8) * N + cI) = __halves2half2(h0, h1);
                *(__half2*)(Rl + (size_t)(r + 8) * N + cI) = __halves2half2(l0, l1);
            }
        }
    }
}

// ---------------- fp32 -> fp16 hi/lo split (prep) ---------------------------
__global__ void split_kernel(const float* __restrict__ src,
                             __half* __restrict__ hi, __half* __restrict__ lo,
                             int n)
{
    int i = (blockIdx.x * blockDim.x + threadIdx.x) * 4;
    if (i >= n) return;
    float4 v = *(const float4*)(src + i);
    __half h0, l0, h1, l1, h2, l2, h3, l3;
    split1(v.x, h0, l0); split1(v.y, h1, l1);
    split1(v.z, h2, l2); split1(v.w, h3, l3);
    *(__half2*)(hi + i)     = __halves2half2(h0, h1);
    *(__half2*)(hi + i + 2) = __halves2half2(h2, h3);
    *(__half2*)(lo + i)     = __halves2half2(l0, l1);
    *(__half2*)(lo + i + 2) = __halves2half2(l2, l3);
}

// ---------------- GRU gate fusion (r,z,n order) -----------------------------
__global__ void gru_gates_kernel(const float* __restrict__ gh,
                                 const float* __restrict__ x, int ldx,
                                 const float* __restrict__ hprev, int ldh,
                                 const float* __restrict__ w_ih,   // [3H,4]
                                 const float* __restrict__ b_ih,   // [3H]
                                 float* __restrict__ hf,           // fp32 (or null)
                                 __half* __restrict__ ph,          // hi plane
                                 __half* __restrict__ pl,          // lo plane
                                 int ldp)
{
    int j = blockIdx.x * blockDim.x + threadIdx.x;   // 0..H-1
    int b = blockIdx.y;
    float4 xv = *(const float4*)(x + (size_t)b * ldx);

    float ig[3];
#pragma unroll
    for (int g = 0; g < 3; ++g) {
        int rI = g * HH + j;
        float4 w = *(const float4*)(w_ih + (size_t)rI * 4);
        ig[g] = b_ih[rI] + xv.x * w.x + xv.y * w.y + xv.z * w.z + xv.w * w.w;
    }
    const float* ghb = gh + (size_t)b * (3 * HH);
    float gr = ghb[j], gz = ghb[HH + j], gn = ghb[2 * HH + j];
    float r = 1.f / (1.f + expf(-(ig[0] + gr)));
    float z = 1.f / (1.f + expf(-(ig[1] + gz)));
    float n = tanhf(ig[2] + r * gn);
    float hp = hprev[(size_t)b * ldh + j];
    float h = (1.f - z) * n + z * hp;

    if (hf) hf[(size_t)b * HH + j] = h;
    __half hh_, hl_;
    split1(h, hh_, hl_);
    ph[(size_t)b * ldp + j] = hh_;
    pl[(size_t)b * ldp + j] = hl_;
}

// ---------------- MLP layer 2 (FF->4), xy accumulate, output write ----------
__global__ void mlp2_kernel(const float* __restrict__ t,   // [B,FF]
                            const float* __restrict__ w2,  // [4,FF]
                            const float* __restrict__ b2,  // [4]
                            float* __restrict__ xy,        // [B,4]
                            float* __restrict__ out,       // [B,HOR,4]
                            int step)
{
    int warp = (blockIdx.x * blockDim.x + threadIdx.x) >> 5;
    int lane = threadIdx.x & 31;
    if (warp >= NB) return;
    const float* tr = t + (size_t)warp * NFF;
    float s0 = 0.f, s1 = 0.f, s2 = 0.f, s3 = 0.f;
    for (int k = lane * 4; k < NFF; k += 128) {
        float4 tv = *(const float4*)(tr + k);
        float4 wa = *(const float4*)(w2 + 0 * NFF + k);
        float4 wb = *(const float4*)(w2 + 1 * NFF + k);
        float4 wc = *(const float4*)(w2 + 2 * NFF + k);
        float4 wd = *(const float4*)(w2 + 3 * NFF + k);
        s0 += tv.x * wa.x + tv.y * wa.y + tv.z * wa.z + tv.w * wa.w;
        s1 += tv.x * wb.x + tv.y * wb.y + tv.z * wb.z + tv.w * wb.w;
        s2 += tv.x * wc.x + tv.y * wc.y + tv.z * wc.z + tv.w * wc.w;
        s3 += tv.x * wd.x + tv.y * wd.y + tv.z * wd.z + tv.w * wd.w;
    }
#pragma unroll
    for (int off = 16; off > 0; off >>= 1) {
        s0 += __shfl_xor_sync(0xffffffffu, s0, off);
        s1 += __shfl_xor_sync(0xffffffffu, s1, off);
        s2 += __shfl_xor_sync(0xffffffffu, s2, off);
        s3 += __shfl_xor_sync(0xffffffffu, s3, off);
    }
    if (lane == 0) {
        float4 cur = *(float4*)(xy + (size_t)warp * 4);
        cur.x += s0 + b2[0];
        cur.y += s1 + b2[1];
        cur.z += s2 + b2[2];
        cur.w += s3 + b2[3];
        *(float4*)(xy + (size_t)warp * 4) = cur;
        *(float4*)(out + (size_t)warp * NHOR * NOUT + step * NOUT) = cur;
    }
}

__global__ void zero_kernel(float* __restrict__ p, int n)
{
    int i = blockIdx.x * blockDim.x + threadIdx.x;
    if (i < n) p[i] = 0.f;
}

// ---------------- launch -----------------------------------------------------
extern "C" void kernel_launch(void* const* d_in, const int* in_sizes, int n_in,
                              void* d_out, int out_size)
{
    const float* pv   = (const float*)d_in[0];
    const float* ptf  = (const float*)d_in[1];
    const float* w_ih = (const float*)d_in[2];
    const float* w_hh = (const float*)d_in[3];
    const float* b_ih = (const float*)d_in[4];
    const float* b_hh = (const float*)d_in[5];
    const float* w_fc = (const float*)d_in[6];
    const float* b_fc = (const float*)d_in[7];
    const float* w1   = (const float*)d_in[8];
    const float* b1   = (const float*)d_in[9];
    const float* w2   = (const float*)d_in[10];
    const float* b2   = (const float*)d_in[11];
    float* out = (float*)d_out;

    float *gh, *hx, *h1, *xy, *tt;
    __half *hp_h, *hp_l, *hc_h, *hc_l, *hr_h, *hr_l;
    __half *whh_h, *whh_l, *wfc_h, *wfc_l, *w1_h, *w1_l;
    cudaGetSymbolAddress((void**)&gh, g_gh);
    cudaGetSymbolAddress((void**)&hx, g_hx);
    cudaGetSymbolAddress((void**)&h1, g_h1);
    cudaGetSymbolAddress((void**)&xy, g_xy);
    cudaGetSymbolAddress((void**)&tt, g_t);
    cudaGetSymbolAddress((void**)&hp_h, g_hp_h);
    cudaGetSymbolAddress((void**)&hp_l, g_hp_l);
    cudaGetSymbolAddress((void**)&hc_h, g_hc_h);
    cudaGetSymbolAddress((void**)&hc_l, g_hc_l);
    cudaGetSymbolAddress((void**)&hr_h, g_hr_h);
    cudaGetSymbolAddress((void**)&hr_l, g_hr_l);
    cudaGetSymbolAddress((void**)&whh_h, g_whh_h);
    cudaGetSymbolAddress((void**)&whh_l, g_whh_l);
    cudaGetSymbolAddress((void**)&wfc_h, g_wfc_h);
    cudaGetSymbolAddress((void**)&wfc_l, g_wfc_l);
    cudaGetSymbolAddress((void**)&w1_h, g_w1_h);
    cudaGetSymbolAddress((void**)&w1_l, g_w1_l);

    cudaFuncSetAttribute(hgemm<0, 0>, cudaFuncAttributeMaxDynamicSharedMemorySize, SMEM_DYN);
    cudaFuncSetAttribute(hgemm<0, 1>, cudaFuncAttributeMaxDynamicSharedMemorySize, SMEM_DYN);
    cudaFuncSetAttribute(hgemm<1, 0>, cudaFuncAttributeMaxDynamicSharedMemorySize, SMEM_DYN);

    // ---- prep: split weights + initial hprev (ptf) ----
    split_kernel<<<(3 * HH * HH / 4 + 255) / 256, 256>>>(w_hh, whh_h, whh_l, 3 * HH * HH);
    split_kernel<<<(HH * 2 * HH / 4 + 255) / 256, 256>>>(w_fc, wfc_h, wfc_l, HH * 2 * HH);
    split_kernel<<<(NFF * HH / 4 + 255) / 256, 256>>>(w1, w1_h, w1_l, NFF * HH);
    split_kernel<<<(NB * HH / 4 + 255) / 256, 256>>>(ptf, hp_h, hp_l, NB * HH);
    zero_kernel<<<(NB * NOUT) / 256, 256>>>(xy, NB * NOUT);

    const float* hprev_f32 = ptf;
    for (int i = 0; i < NHOR; ++i) {
        // cell 1: gh = hprev @ w_hh^T + b_hh ; h1 = gates(xy, gh, hprev)
        hgemm<0, 0><<<dim3(3 * HH / 128, NB / 128), 256, SMEM_DYN>>>(
            hp_h, hp_l, HH, whh_h, whh_l, HH, b_hh, gh, 3 * HH,
            nullptr, nullptr, nullptr, nullptr);
        gru_gates_kernel<<<dim3(HH / 256, NB), 256>>>(
            gh, xy, NOUT, hprev_f32, HH, w_ih, b_ih,
            h1, hc_h, hc_l, 2 * HH);

        // cell 2: gh = h1 @ w_hh^T + b_hh ; h2 = gates(pv_i, gh, h1)
        hgemm<0, 0><<<dim3(3 * HH / 128, NB / 128), 256, SMEM_DYN>>>(
            hc_h, hc_l, 2 * HH, whh_h, whh_l, HH, b_hh, gh, 3 * HH,
            nullptr, nullptr, nullptr, nullptr);
        gru_gates_kernel<<<dim3(HH / 256, NB), 256>>>(
            gh, pv + i * NOUT, NHOR * NOUT, h1, HH, w_ih, b_ih,
            nullptr, hc_h + HH, hc_l + HH, 2 * HH);

        // hx = hcat @ w_fc^T + b_fc ; emit hx fp32 + split planes + relu planes
        hgemm<0, 1><<<dim3(HH / 128, NB / 128), 256, SMEM_DYN>>>(
            hc_h, hc_l, 2 * HH, wfc_h, wfc_l, 2 * HH, b_fc, hx, HH,
            hp_h, hp_l, hr_h, hr_l);

        // t = relu(relu(hx) @ w1^T + b1)
        hgemm<1, 0><<<dim3(NFF / 128, NB / 128), 256, SMEM_DYN>>>(
            hr_h, hr_l, HH, w1_h, w1_l, HH, b1, tt, NFF,
            nullptr, nullptr, nullptr, nullptr);

        // xy += t @ w2^T + b2 ; out[:, i, :] = xy
        mlp2_kernel<<<(NB * 32) / 256, 256>>>(tt, w2, b2, xy, out, i);

        hprev_f32 = hx;
    }
}

// round 8
// speedup vs baseline: 2.8761x; 1.1327x over previous
#include <cuda_runtime.h>
#include <cuda_fp16.h>
#include <math.h>
#include <stdint.h>

#define NB   16384
#define HH   512
#define NOUT 4
#define NFF  2048
#define NHOR 5

// ---------------- fp32 scratch ----------------------------------------------
__device__ float g_gh[(size_t)NB * 3 * HH];   // gate pre-activations [B,3H]
__device__ float g_hx[(size_t)NB * HH];       // hx fp32 (gates hprev)
__device__ float g_h1[(size_t)NB * HH];       // h1 fp32 (cell-2 gates hprev)
__device__ float g_xy[(size_t)NB * NOUT];     // running xy
__device__ float g_part[(size_t)NB * 16 * NOUT];  // mlp partials [B,16,4]

// ---------------- fp16 hi/lo planes (GEMM operands) -------------------------
__device__ __align__(16) __half g_hp_h[(size_t)NB * HH];      // hprev
__device__ __align__(16) __half g_hp_l[(size_t)NB * HH];
__device__ __align__(16) __half g_hc_h[(size_t)NB * 2 * HH];  // hcat [h1|h2]
__device__ __align__(16) __half g_hc_l[(size_t)NB * 2 * HH];
__device__ __align__(16) __half g_hr_h[(size_t)NB * HH];      // relu(hx)
__device__ __align__(16) __half g_hr_l[(size_t)NB * HH];
__device__ __align__(16) __half g_whh_h[3 * HH * HH];
__device__ __align__(16) __half g_whh_l[3 * HH * HH];
__device__ __align__(16) __half g_wfc_h[HH * 2 * HH];
__device__ __align__(16) __half g_wfc_l[HH * 2 * HH];
__device__ __align__(16) __half g_w1_h[NFF * HH];
__device__ __align__(16) __half g_w1_l[NFF * HH];

// ---------------- helpers ---------------------------------------------------
__device__ __forceinline__ uint32_t smem_u32(const void* p) {
    uint32_t a;
    asm("{ .reg .u64 t; cvta.to.shared.u64 t, %1; cvt.u32.u64 %0, t; }"
        : "=r"(a) : "l"(p));
    return a;
}
__device__ __forceinline__ void split1(float x, __half& h, __half& l) {
    h = __float2half_rn(x);
    l = __float2half_rn(x - __half2float(h));
}
__device__ __forceinline__ void ldsm4(uint32_t& r0, uint32_t& r1,
                                      uint32_t& r2, uint32_t& r3, uint32_t addr) {
    asm volatile("ldmatrix.sync.aligned.m8n8.x4.shared.b16 {%0,%1,%2,%3}, [%4];"
                 : "=r"(r0), "=r"(r1), "=r"(r2), "=r"(r3) : "r"(addr));
}
__device__ __forceinline__ void hmma(float* d, const uint32_t* a,
                                     uint32_t b0, uint32_t b1) {
    asm volatile(
        "mma.sync.aligned.m16n8k16.row.col.f32.f16.f16.f32 "
        "{%0,%1,%2,%3}, {%4,%5,%6,%7}, {%8,%9}, {%0,%1,%2,%3};"
        : "+f"(d[0]), "+f"(d[1]), "+f"(d[2]), "+f"(d[3])
        : "r"(a[0]), "r"(a[1]), "r"(a[2]), "r"(a[3]), "r"(b0), "r"(b1));
}
__device__ __forceinline__ void cpasync16(uint32_t dst, const void* src) {
    asm volatile("cp.async.cg.shared.global [%0], [%1], 16;" :: "r"(dst), "l"(src));
}

// smem plane: 128 rows x 32 fp16 = 64B/row; XOR swizzle keeps LDGSTS stores and
// ldmatrix reads conflict-free without padding.
#define BK      32
#define STAGES  3
#define PL      8192            // one plane: 128*64B
#define STG     (4 * PL)        // Ah, Al, Wh, Wl
#define SMEM_DYN (STAGES * STG) // 96 KB

__device__ __forceinline__ uint32_t sw_addr(uint32_t base, int row, int cgrp) {
    return base + row * 64 + (uint32_t)((cgrp ^ ((row >> 1) & 3)) << 4);
}

// =====================  split-fp16 HMMA GEMM, cp.async 3-stage  =============
// C[B,N] = act(A @ W^T + bias); A,W given as fp16 hi/lo planes.
// PASSES=3: hh + hl + lh (~fp32). PASSES=2: (hi+lo)*W_hi (~2^-12).
// FUSED=1: no C store; reduce relu(tile) against w2 into partials [B,16,4].
template <int RELU_C, int WSPLITS, int PASSES, int FUSED>
__global__ __launch_bounds__(256, 2)
void hgemm(const __half* __restrict__ Ah, const __half* __restrict__ Al, int lda,
           const __half* __restrict__ Wh, const __half* __restrict__ Wl, int K,
           const float* __restrict__ bias, float* __restrict__ C, int N,
           __half* __restrict__ Oh, __half* __restrict__ Ol,
           __half* __restrict__ Rh, __half* __restrict__ Rl,
           const float* __restrict__ w2g, float* __restrict__ part)
{
    extern __shared__ char dsm[];
    const uint32_t sb = smem_u32(dsm);

    const int tid  = threadIdx.x;
    const int wid  = tid >> 5;
    const int lane = tid & 31;
    const int wm   = wid & 1;
    const int wn   = wid >> 1;
    const int grp  = lane >> 3;
    const int wi   = lane & 7;

    const __half* Abh = Ah + (size_t)blockIdx.y * 128 * lda;
    const __half* Abl = Al + (size_t)blockIdx.y * 128 * lda;
    const __half* Wbh = Wh + (size_t)blockIdx.x * 128 * K;
    const __half* Wbl = Wl + (size_t)blockIdx.x * 128 * K;

    const int r0c = tid >> 2, cg0 = tid & 3;
    const int r1c = (tid + 256) >> 2, cg1 = tid & 3;

    const int rowA0 = wm * 64 + (grp & 1) * 8 + wi;
    const int sA    = (rowA0 >> 1) & 3;
    const int cA    = grp >> 1;
    const int rowW0 = wn * 32 + (grp >> 1) * 8 + wi;
    const int sW    = (rowW0 >> 1) & 3;
    const int cW    = grp & 1;

    float acc[4][4][4];
#pragma unroll
    for (int mt = 0; mt < 4; ++mt)
#pragma unroll
        for (int nt = 0; nt < 4; ++nt)
#pragma unroll
            for (int r = 0; r < 4; ++r) acc[mt][nt][r] = 0.f;

    const int nchunk = K >> 5;   // K / 32

#define ISSUE(c) do {                                                          \
    int k0_ = (c) << 5;                                                        \
    uint32_t stg_ = sb + (uint32_t)((c) % STAGES) * STG;                       \
    uint32_t d0_ = sw_addr(stg_, r0c, cg0);                                    \
    cpasync16(d0_,          Abh + (size_t)r0c * lda + k0_ + cg0 * 8);          \
    cpasync16(d0_ + PL,     Abl + (size_t)r0c * lda + k0_ + cg0 * 8);          \
    cpasync16(d0_ + 2*PL,   Wbh + (size_t)r0c * K  + k0_ + cg0 * 8);           \
    if (PASSES == 3)                                                           \
        cpasync16(d0_ + 3*PL, Wbl + (size_t)r0c * K + k0_ + cg0 * 8);          \
    uint32_t d1_ = sw_addr(stg_, r1c, cg1);                                    \
    cpasync16(d1_,          Abh + (size_t)r1c * lda + k0_ + cg1 * 8);          \
    cpasync16(d1_ + PL,     Abl + (size_t)r1c * lda + k0_ + cg1 * 8);          \
    cpasync16(d1_ + 2*PL,   Wbh + (size_t)r1c * K  + k0_ + cg1 * 8);           \
    if (PASSES == 3)                                                           \
        cpasync16(d1_ + 3*PL, Wbl + (size_t)r1c * K + k0_ + cg1 * 8);          \
} while (0)

#pragma unroll
    for (int s = 0; s < STAGES - 1; ++s) {
        ISSUE(s);
        asm volatile("cp.async.commit_group;");
    }

    for (int c = 0; c < nchunk; ++c) {
        asm volatile("cp.async.wait_group %0;" :: "n"(STAGES - 2));
        __syncthreads();
        if (c + STAGES - 1 < nchunk) ISSUE(c + STAGES - 1);
        asm volatile("cp.async.commit_group;");

        const uint32_t stg = sb + (uint32_t)(c % STAGES) * STG;
#pragma unroll
        for (int ks = 0; ks < 2; ++ks) {
            uint32_t a[4][4];
            uint32_t bh[4][2], bl[4][2];
#pragma unroll
            for (int mt = 0; mt < 4; ++mt) {
                uint32_t ad = stg + (uint32_t)(rowA0 + mt * 16) * 64
                            + (uint32_t)(((ks * 2 + cA) ^ sA) << 4);
                ldsm4(a[mt][0], a[mt][1], a[mt][2], a[mt][3], ad);
            }
#pragma unroll
            for (int nh = 0; nh < 2; ++nh) {
                uint32_t wd = stg + 2 * PL + (uint32_t)(rowW0 + nh * 16) * 64
                            + (uint32_t)(((ks * 2 + cW) ^ sW) << 4);
                uint32_t r0, r1, r2, r3;
                ldsm4(r0, r1, r2, r3, wd);
                bh[nh * 2 + 0][0] = r0; bh[nh * 2 + 0][1] = r1;
                bh[nh * 2 + 1][0] = r2; bh[nh * 2 + 1][1] = r3;
                if (PASSES == 3) {
                    ldsm4(r0, r1, r2, r3, wd + PL);
                    bl[nh * 2 + 0][0] = r0; bl[nh * 2 + 0][1] = r1;
                    bl[nh * 2 + 1][0] = r2; bl[nh * 2 + 1][1] = r3;
                }
            }
            // A_hi * W_hi (+ A_hi * W_lo when PASSES==3)
#pragma unroll
            for (int mt = 0; mt < 4; ++mt)
#pragma unroll
                for (int nt = 0; nt < 4; ++nt) {
                    hmma(acc[mt][nt], a[mt], bh[nt][0], bh[nt][1]);
                    if (PASSES == 3)
                        hmma(acc[mt][nt], a[mt], bl[nt][0], bl[nt][1]);
                }
            // A_lo * W_hi
#pragma unroll
            for (int mt = 0; mt < 4; ++mt) {
                uint32_t ad = stg + PL + (uint32_t)(rowA0 + mt * 16) * 64
                            + (uint32_t)(((ks * 2 + cA) ^ sA) << 4);
                ldsm4(a[mt][0], a[mt][1], a[mt][2], a[mt][3], ad);
            }
#pragma unroll
            for (int mt = 0; mt < 4; ++mt)
#pragma unroll
                for (int nt = 0; nt < 4; ++nt)
                    hmma(acc[mt][nt], a[mt], bh[nt][0], bh[nt][1]);
        }
    }
#undef ISSUE

    if (FUSED) {
        // ---- fused mlp2: relu(tile) . w2 -> partials [B, 16, 4] ------------
        __syncthreads();                       // pipeline smem now reusable
        float* w2s = (float*)dsm;              // [4][128]
        float* red = (float*)(dsm + 2048);     // [4 warps-n][128 rows][4 outs]
        if (tid < 128) {
#pragma unroll
            for (int o = 0; o < 4; ++o)
                w2s[o * 128 + tid] = w2g[(size_t)o * NFF + blockIdx.x * 128 + tid];
        }
        __syncthreads();

        float po[8][4];
#pragma unroll
        for (int i = 0; i < 8; ++i)
#pragma unroll
            for (int o = 0; o < 4; ++o) po[i][o] = 0.f;

#pragma unroll
        for (int mt = 0; mt < 4; ++mt) {
#pragma unroll
            for (int nt = 0; nt < 4; ++nt) {
                const int clb = wn * 32 + (lane & 3) * 2 + nt * 8;
                const float b0 = bias[blockIdx.x * 128 + clb];
                const float b1v = bias[blockIdx.x * 128 + clb + 1];
                float t00 = fmaxf(acc[mt][nt][0] + b0, 0.f);
                float t01 = fmaxf(acc[mt][nt][1] + b1v, 0.f);
                float t10 = fmaxf(acc[mt][nt][2] + b0, 0.f);
                float t11 = fmaxf(acc[mt][nt][3] + b1v, 0.f);
#pragma unroll
                for (int o = 0; o < 4; ++o) {
                    float w0 = w2s[o * 128 + clb], w1w = w2s[o * 128 + clb + 1];
                    po[mt * 2 + 0][o] += t00 * w0 + t01 * w1w;
                    po[mt * 2 + 1][o] += t10 * w0 + t11 * w1w;
                }
            }
        }
        // quad butterfly (lanes sharing rows)
#pragma unroll
        for (int off = 1; off <= 2; off <<= 1)
#pragma unroll
            for (int i = 0; i < 8; ++i)
#pragma unroll
                for (int o = 0; o < 4; ++o)
                    po[i][o] += __shfl_xor_sync(0xffffffffu, po[i][o], off);

        if ((lane & 3) == 0) {
            const int rq = lane >> 2;
#pragma unroll
            for (int i = 0; i < 8; ++i) {
                int row = wm * 64 + rq + (i >> 1) * 16 + (i & 1) * 8;
#pragma unroll
                for (int o = 0; o < 4; ++o)
                    red[(wn * 128 + row) * 4 + o] = po[i][o];
            }
        }
        __syncthreads();
        if (tid < 128) {
            float4 s = make_float4(0.f, 0.f, 0.f, 0.f);
#pragma unroll
            for (int w = 0; w < 4; ++w) {
                float4 v = *(float4*)&red[(w * 128 + tid) * 4];
                s.x += v.x; s.y += v.y; s.z += v.z; s.w += v.w;
            }
            *(float4*)(part + ((size_t)(blockIdx.y * 128 + tid) * 16
                               + blockIdx.x) * 4) = s;
        }
        return;
    }

    // ---- standard epilogue -------------------------------------------------
    const int row0 = blockIdx.y * 128 + wm * 64 + (lane >> 2);
    const int col0 = blockIdx.x * 128 + wn * 32 + (lane & 3) * 2;
#pragma unroll
    for (int mt = 0; mt < 4; ++mt) {
#pragma unroll
        for (int nt = 0; nt < 4; ++nt) {
            const int cI = col0 + nt * 8;
            const float b0 = bias[cI], b1 = bias[cI + 1];
            float2 v0, v1;
            v0.x = acc[mt][nt][0] + b0; v0.y = acc[mt][nt][1] + b1;
            v1.x = acc[mt][nt][2] + b0; v1.y = acc[mt][nt][3] + b1;
            if (RELU_C) {
                v0.x = fmaxf(v0.x, 0.f); v0.y = fmaxf(v0.y, 0.f);
                v1.x = fmaxf(v1.x, 0.f); v1.y = fmaxf(v1.y, 0.f);
            }
            const int r = row0 + mt * 16;
            *(float2*)(C + (size_t)r * N + cI)       = v0;
            *(float2*)(C + (size_t)(r + 8) * N + cI) = v1;
            if (WSPLITS) {
                __half h0, l0, h1, l1;
                split1(v0.x, h0, l0); split1(v0.y, h1, l1);
                *(__half2*)(Oh + (size_t)r * N + cI) = __halves2half2(h0, h1);
                *(__half2*)(Ol + (size_t)r * N + cI) = __halves2half2(l0, l1);
                split1(v1.x, h0, l0); split1(v1.y, h1, l1);
                *(__half2*)(Oh + (size_t)(r + 8) * N + cI) = __halves2half2(h0, h1);
                *(__half2*)(Ol + (size_t)(r + 8) * N + cI) = __halves2half2(l0, l1);
                float r0x = fmaxf(v0.x, 0.f), r0y = fmaxf(v0.y, 0.f);
                float r1x = fmaxf(v1.x, 0.f), r1y = fmaxf(v1.y, 0.f);
                split1(r0x, h0, l0); split1(r0y, h1, l1);
                *(__half2*)(Rh + (size_t)r * N + cI) = __halves2half2(h0, h1);
                *(__half2*)(Rl + (size_t)r * N + cI) = __halves2half2(l0, l1);
                split1(r1x, h0, l0); split1(r1y, h1, l1);
                *(__half2*)(Rh + (size_t)(r + 8) * N + cI) = __halves2half2(h0, h1);
                *(__half2*)(Rl + (size_t)(r + 8) * N + cI) = __halves2half2(l0, l1);
            }
        }
    }
}

// ---------------- prep: all weight/state splits + xy zero, ONE launch -------
__global__ void prep_kernel(const float* __restrict__ whh, const float* __restrict__ wfc,
                            const float* __restrict__ w1f, const float* __restrict__ ptf,
                            __half* __restrict__ whh_h, __half* __restrict__ whh_l,
                            __half* __restrict__ wfc_h, __half* __restrict__ wfc_l,
                            __half* __restrict__ w1_h,  __half* __restrict__ w1_l,
                            __half* __restrict__ hp_h,  __half* __restrict__ hp_l,
                            float* __restrict__ xy)
{
    const int n0 = 3 * HH * HH;
    const int n1 = n0 + HH * 2 * HH;
    const int n2 = n1 + NFF * HH;
    const int n3 = n2 + NB * HH;
    const int n4 = n3 + NB * NOUT;
    int i = (blockIdx.x * blockDim.x + threadIdx.x) * 4;
    if (i >= n4) return;
    if (i >= n3) {
        *(float4*)(xy + (i - n3)) = make_float4(0.f, 0.f, 0.f, 0.f);
        return;
    }
    const float* src; __half *hi, *lo; int off;
    if (i < n0)      { src = whh; hi = whh_h; lo = whh_l; off = i; }
    else if (i < n1) { src = wfc; hi = wfc_h; lo = wfc_l; off = i - n0; }
    else if (i < n2) { src = w1f; hi = w1_h;  lo = w1_l;  off = i - n1; }
    else             { src = ptf; hi = hp_h;  lo = hp_l;  off = i - n2; }
    float4 v = *(const float4*)(src + off);
    __half h0, l0, h1, l1, h2, l2, h3, l3;
    split1(v.x, h0, l0); split1(v.y, h1, l1);
    split1(v.z, h2, l2); split1(v.w, h3, l3);
    *(__half2*)(hi + off)     = __halves2half2(h0, h1);
    *(__half2*)(hi + off + 2) = __halves2half2(h2, h3);
    *(__half2*)(lo + off)     = __halves2half2(l0, l1);
    *(__half2*)(lo + off + 2) = __halves2half2(l2, l3);
}

// ---------------- GRU gate fusion (r,z,n order) -----------------------------
__global__ void gru_gates_kernel(const float* __restrict__ gh,
                                 const float* __restrict__ x, int ldx,
                                 const float* __restrict__ hprev, int ldh,
                                 const float* __restrict__ w_ih,   // [3H,4]
                                 const float* __restrict__ b_ih,   // [3H]
                                 float* __restrict__ hf,           // fp32 (or null)
                                 __half* __restrict__ ph,          // hi plane
                                 __half* __restrict__ pl,          // lo plane
                                 int ldp)
{
    int j = blockIdx.x * blockDim.x + threadIdx.x;   // 0..H-1
    int b = blockIdx.y;
    float4 xv = *(const float4*)(x + (size_t)b * ldx);

    float ig[3];
#pragma unroll
    for (int g = 0; g < 3; ++g) {
        int rI = g * HH + j;
        float4 w = *(const float4*)(w_ih + (size_t)rI * 4);
        ig[g] = b_ih[rI] + xv.x * w.x + xv.y * w.y + xv.z * w.z + xv.w * w.w;
    }
    const float* ghb = gh + (size_t)b * (3 * HH);
    float gr = ghb[j], gz = ghb[HH + j], gn = ghb[2 * HH + j];
    float r = 1.f / (1.f + expf(-(ig[0] + gr)));
    float z = 1.f / (1.f + expf(-(ig[1] + gz)));
    float n = tanhf(ig[2] + r * gn);
    float hp = hprev[(size_t)b * ldh + j];
    float h = (1.f - z) * n + z * hp;

    if (hf) hf[(size_t)b * HH + j] = h;
    __half hh_, hl_;
    split1(h, hh_, hl_);
    ph[(size_t)b * ldp + j] = hh_;
    pl[(size_t)b * ldp + j] = hl_;
}

// ---------------- finalize: sum partials, update xy, write out --------------
__global__ void finalize_kernel(const float* __restrict__ part,
                                const float* __restrict__ b2,
                                float* __restrict__ xy,
                                float* __restrict__ out, int step)
{
    int b = blockIdx.x * blockDim.x + threadIdx.x;
    if (b >= NB) return;
    const float4* p = (const float4*)(part + (size_t)b * 64);
    float4 s = p[0];
#pragma unroll
    for (int j = 1; j < 16; ++j) {
        float4 v = p[j];
        s.x += v.x; s.y += v.y; s.z += v.z; s.w += v.w;
    }
    float4 cur = *(float4*)(xy + (size_t)b * 4);
    cur.x += s.x + b2[0];
    cur.y += s.y + b2[1];
    cur.z += s.z + b2[2];
    cur.w += s.w + b2[3];
    *(float4*)(xy + (size_t)b * 4) = cur;
    *(float4*)(out + (size_t)b * NHOR * NOUT + step * NOUT) = cur;
}

// ---------------- launch -----------------------------------------------------
extern "C" void kernel_launch(void* const* d_in, const int* in_sizes, int n_in,
                              void* d_out, int out_size)
{
    const float* pv   = (const float*)d_in[0];
    const float* ptf  = (const float*)d_in[1];
    const float* w_ih = (const float*)d_in[2];
    const float* w_hh = (const float*)d_in[3];
    const float* b_ih = (const float*)d_in[4];
    const float* b_hh = (const float*)d_in[5];
    const float* w_fc = (const float*)d_in[6];
    const float* b_fc = (const float*)d_in[7];
    const float* w1   = (const float*)d_in[8];
    const float* b1   = (const float*)d_in[9];
    const float* w2   = (const float*)d_in[10];
    const float* b2   = (const float*)d_in[11];
    float* out = (float*)d_out;

    float *gh, *hx, *h1, *xy, *part;
    __half *hp_h, *hp_l, *hc_h, *hc_l, *hr_h, *hr_l;
    __half *whh_h, *whh_l, *wfc_h, *wfc_l, *w1_h, *w1_l;
    cudaGetSymbolAddress((void**)&gh, g_gh);
    cudaGetSymbolAddress((void**)&hx, g_hx);
    cudaGetSymbolAddress((void**)&h1, g_h1);
    cudaGetSymbolAddress((void**)&xy, g_xy);
    cudaGetSymbolAddress((void**)&part, g_part);
    cudaGetSymbolAddress((void**)&hp_h, g_hp_h);
    cudaGetSymbolAddress((void**)&hp_l, g_hp_l);
    cudaGetSymbolAddress((void**)&hc_h, g_hc_h);
    cudaGetSymbolAddress((void**)&hc_l, g_hc_l);
    cudaGetSymbolAddress((void**)&hr_h, g_hr_h);
    cudaGetSymbolAddress((void**)&hr_l, g_hr_l);
    cudaGetSymbolAddress((void**)&whh_h, g_whh_h);
    cudaGetSymbolAddress((void**)&whh_l, g_whh_l);
    cudaGetSymbolAddress((void**)&wfc_h, g_wfc_h);
    cudaGetSymbolAddress((void**)&wfc_l, g_wfc_l);
    cudaGetSymbolAddress((void**)&w1_h, g_w1_h);
    cudaGetSymbolAddress((void**)&w1_l, g_w1_l);

    cudaFuncSetAttribute(hgemm<0, 0, 3, 0>, cudaFuncAttributeMaxDynamicSharedMemorySize, SMEM_DYN);
    cudaFuncSetAttribute(hgemm<0, 1, 3, 0>, cudaFuncAttributeMaxDynamicSharedMemorySize, SMEM_DYN);
    cudaFuncSetAttribute(hgemm<0, 0, 2, 1>, cudaFuncAttributeMaxDynamicSharedMemorySize, SMEM_DYN);

    // ---- prep (single launch): split weights + ptf, zero xy ----
    {
        const int n4 = 3 * HH * HH + HH * 2 * HH + NFF * HH + NB * HH + NB * NOUT;
        prep_kernel<<<(n4 / 4 + 255) / 256, 256>>>(
            w_hh, w_fc, w1, ptf,
            whh_h, whh_l, wfc_h, wfc_l, w1_h, w1_l, hp_h, hp_l, xy);
    }

    const float* hprev_f32 = ptf;
    for (int i = 0; i < NHOR; ++i) {
        // cell 1: gh = hprev @ w_hh^T + b_hh ; h1 = gates(xy, gh, hprev)
        hgemm<0, 0, 3, 0><<<dim3(3 * HH / 128, NB / 128), 256, SMEM_DYN>>>(
            hp_h, hp_l, HH, whh_h, whh_l, HH, b_hh, gh, 3 * HH,
            nullptr, nullptr, nullptr, nullptr, nullptr, nullptr);
        gru_gates_kernel<<<dim3(HH / 256, NB), 256>>>(
            gh, xy, NOUT, hprev_f32, HH, w_ih, b_ih,
            h1, hc_h, hc_l, 2 * HH);

        // cell 2: gh = h1 @ w_hh^T + b_hh ; h2 = gates(pv_i, gh, h1)
        hgemm<0, 0, 3, 0><<<dim3(3 * HH / 128, NB / 128), 256, SMEM_DYN>>>(
            hc_h, hc_l, 2 * HH, whh_h, whh_l, HH, b_hh, gh, 3 * HH,
            nullptr, nullptr, nullptr, nullptr, nullptr, nullptr);
        gru_gates_kernel<<<dim3(HH / 256, NB), 256>>>(
            gh, pv + i * NOUT, NHOR * NOUT, h1, HH, w_ih, b_ih,
            nullptr, hc_h + HH, hc_l + HH, 2 * HH);

        // hx = hcat @ w_fc^T + b_fc ; emit hx fp32 + hp planes + relu planes
        hgemm<0, 1, 3, 0><<<dim3(HH / 128, NB / 128), 256, SMEM_DYN>>>(
            hc_h, hc_l, 2 * HH, wfc_h, wfc_l, 2 * HH, b_fc, hx, HH,
            hp_h, hp_l, hr_h, hr_l, nullptr, nullptr);

        // fused: t = relu(relu(hx) @ w1^T + b1); partials = t-tile . w2
        hgemm<0, 0, 2, 1><<<dim3(NFF / 128, NB / 128), 256, SMEM_DYN>>>(
            hr_h, hr_l, HH, w1_h, w1_l, HH, b1, nullptr, NFF,
            nullptr, nullptr, nullptr, nullptr, w2, part);

        // xy += sum(partials) + b2 ; out[:, i, :] = xy
        finalize_kernel<<<(NB + 255) / 256, 256>>>(part, b2, xy, out, i);

        hprev_f32 = hx;
    }
}

// round 9
// speedup vs baseline: 2.9415x; 1.0227x over previous
#include <cuda_runtime.h>
#include <cuda_fp16.h>
#include <math.h>
#include <stdint.h>

#define NB   16384
#define HH   512
#define NOUT 4
#define NFF  2048
#define NHOR 5

// ---------------- fp32 scratch ----------------------------------------------
__device__ float g_gh[(size_t)NB * 3 * HH];       // gate pre-activations [B,3H]
__device__ float g_xy[(size_t)NB * NOUT];         // running xy
__device__ float g_part[(size_t)NB * 16 * NOUT];  // mlp partials [B,16,4]

// ---------------- fp16 hi/lo planes (GEMM operands) -------------------------
__device__ __align__(16) __half g_hp_h[(size_t)NB * HH];      // hprev (hx)
__device__ __align__(16) __half g_hp_l[(size_t)NB * HH];
__device__ __align__(16) __half g_hc_h[(size_t)NB * 2 * HH];  // hcat [h1|h2]
__device__ __align__(16) __half g_hc_l[(size_t)NB * 2 * HH];
__device__ __align__(16) __half g_hr_h[(size_t)NB * HH];      // relu(hx)
__device__ __align__(16) __half g_hr_l[(size_t)NB * HH];
__device__ __align__(16) __half g_whh_h[3 * HH * HH];
__device__ __align__(16) __half g_whh_l[3 * HH * HH];
__device__ __align__(16) __half g_wfc_h[HH * 2 * HH];
__device__ __align__(16) __half g_wfc_l[HH * 2 * HH];
__device__ __align__(16) __half g_w1_h[NFF * HH];
__device__ __align__(16) __half g_w1_l[NFF * HH];

// ---------------- helpers ---------------------------------------------------
__device__ __forceinline__ uint32_t smem_u32(const void* p) {
    uint32_t a;
    asm("{ .reg .u64 t; cvta.to.shared.u64 t, %1; cvt.u32.u64 %0, t; }"
        : "=r"(a) : "l"(p));
    return a;
}
__device__ __forceinline__ void split1(float x, __half& h, __half& l) {
    h = __float2half_rn(x);
    l = __float2half_rn(x - __half2float(h));
}
__device__ __forceinline__ void ldsm4(uint32_t& r0, uint32_t& r1,
                                      uint32_t& r2, uint32_t& r3, uint32_t addr) {
    asm volatile("ldmatrix.sync.aligned.m8n8.x4.shared.b16 {%0,%1,%2,%3}, [%4];"
                 : "=r"(r0), "=r"(r1), "=r"(r2), "=r"(r3) : "r"(addr));
}
__device__ __forceinline__ void hmma(float* d, const uint32_t* a,
                                     uint32_t b0, uint32_t b1) {
    asm volatile(
        "mma.sync.aligned.m16n8k16.row.col.f32.f16.f16.f32 "
        "{%0,%1,%2,%3}, {%4,%5,%6,%7}, {%8,%9}, {%0,%1,%2,%3};"
        : "+f"(d[0]), "+f"(d[1]), "+f"(d[2]), "+f"(d[3])
        : "r"(a[0]), "r"(a[1]), "r"(a[2]), "r"(a[3]), "r"(b0), "r"(b1));
}
__device__ __forceinline__ void cpasync16(uint32_t dst, const void* src) {
    asm volatile("cp.async.cg.shared.global [%0], [%1], 16;" :: "r"(dst), "l"(src));
}

// smem plane: 128 rows x 32 fp16 = 64B/row; XOR swizzle keeps LDGSTS stores and
// ldmatrix reads conflict-free without padding.
#define STAGES  3
#define PL      8192            // one plane: 128*64B
#define STG     (4 * PL)        // Ah, Al, Wh, Wl
#define SMEM_DYN (STAGES * STG) // 96 KB

__device__ __forceinline__ uint32_t sw_addr(uint32_t base, int row, int cgrp) {
    return base + row * 64 + (uint32_t)((cgrp ^ ((row >> 1) & 3)) << 4);
}

// =====================  split-fp16 HMMA GEMM, cp.async 3-stage  =============
// C[B,N] = A @ W^T + bias; A,W given as fp16 hi/lo planes.
// PASSES=3: hh + hl + lh (~fp32). PASSES=2: (hi+lo)*W_hi (~2^-12).
// STORE_C: write fp32 C. WSPLITS: write hi/lo planes of C and relu(C).
// FUSED: no store; reduce relu(tile) against w2 into partials [B,16,4].
template <int STORE_C, int WSPLITS, int PASSES, int FUSED>
__global__ __launch_bounds__(256, 2)
void hgemm(const __half* __restrict__ Ah, const __half* __restrict__ Al, int lda,
           const __half* __restrict__ Wh, const __half* __restrict__ Wl, int K,
           const float* __restrict__ bias, float* __restrict__ C, int N,
           __half* __restrict__ Oh, __half* __restrict__ Ol,
           __half* __restrict__ Rh, __half* __restrict__ Rl,
           const float* __restrict__ w2g, float* __restrict__ part)
{
    extern __shared__ char dsm[];
    const uint32_t sb = smem_u32(dsm);

    const int tid  = threadIdx.x;
    const int wid  = tid >> 5;
    const int lane = tid & 31;
    const int wm   = wid & 1;
    const int wn   = wid >> 1;
    const int grp  = lane >> 3;
    const int wi   = lane & 7;

    const __half* Abh = Ah + (size_t)blockIdx.y * 128 * lda;
    const __half* Abl = Al + (size_t)blockIdx.y * 128 * lda;
    const __half* Wbh = Wh + (size_t)blockIdx.x * 128 * K;
    const __half* Wbl = Wl + (size_t)blockIdx.x * 128 * K;

    const int r0c = tid >> 2, cg0 = tid & 3;
    const int r1c = (tid + 256) >> 2, cg1 = tid & 3;

    const int rowA0 = wm * 64 + (grp & 1) * 8 + wi;
    const int sA    = (rowA0 >> 1) & 3;
    const int cA    = grp >> 1;
    const int rowW0 = wn * 32 + (grp >> 1) * 8 + wi;
    const int sW    = (rowW0 >> 1) & 3;
    const int cW    = grp & 1;

    float acc[4][4][4];
#pragma unroll
    for (int mt = 0; mt < 4; ++mt)
#pragma unroll
        for (int nt = 0; nt < 4; ++nt)
#pragma unroll
            for (int r = 0; r < 4; ++r) acc[mt][nt][r] = 0.f;

    const int nchunk = K >> 5;   // K / 32

#define ISSUE(c) do {                                                          \
    int k0_ = (c) << 5;                                                        \
    uint32_t stg_ = sb + (uint32_t)((c) % STAGES) * STG;                       \
    uint32_t d0_ = sw_addr(stg_, r0c, cg0);                                    \
    cpasync16(d0_,          Abh + (size_t)r0c * lda + k0_ + cg0 * 8);          \
    cpasync16(d0_ + PL,     Abl + (size_t)r0c * lda + k0_ + cg0 * 8);          \
    cpasync16(d0_ + 2*PL,   Wbh + (size_t)r0c * K  + k0_ + cg0 * 8);           \
    if (PASSES == 3)                                                           \
        cpasync16(d0_ + 3*PL, Wbl + (size_t)r0c * K + k0_ + cg0 * 8);          \
    uint32_t d1_ = sw_addr(stg_, r1c, cg1);                                    \
    cpasync16(d1_,          Abh + (size_t)r1c * lda + k0_ + cg1 * 8);          \
    cpasync16(d1_ + PL,     Abl + (size_t)r1c * lda + k0_ + cg1 * 8);          \
    cpasync16(d1_ + 2*PL,   Wbh + (size_t)r1c * K  + k0_ + cg1 * 8);           \
    if (PASSES == 3)                                                           \
        cpasync16(d1_ + 3*PL, Wbl + (size_t)r1c * K + k0_ + cg1 * 8);          \
} while (0)

#pragma unroll
    for (int s = 0; s < STAGES - 1; ++s) {
        ISSUE(s);
        asm volatile("cp.async.commit_group;");
    }

    for (int c = 0; c < nchunk; ++c) {
        asm volatile("cp.async.wait_group %0;" :: "n"(STAGES - 2));
        __syncthreads();
        if (c + STAGES - 1 < nchunk) ISSUE(c + STAGES - 1);
        asm volatile("cp.async.commit_group;");

        const uint32_t stg = sb + (uint32_t)(c % STAGES) * STG;
#pragma unroll
        for (int ks = 0; ks < 2; ++ks) {
            // ---- W fragments first ----
            uint32_t bh[4][2], bl[4][2];
#pragma unroll
            for (int nh = 0; nh < 2; ++nh) {
                uint32_t wd = stg + 2 * PL + (uint32_t)(rowW0 + nh * 16) * 64
                            + (uint32_t)(((ks * 2 + cW) ^ sW) << 4);
                uint32_t r0, r1, r2, r3;
                ldsm4(r0, r1, r2, r3, wd);
                bh[nh * 2 + 0][0] = r0; bh[nh * 2 + 0][1] = r1;
                bh[nh * 2 + 1][0] = r2; bh[nh * 2 + 1][1] = r3;
                if (PASSES == 3) {
                    ldsm4(r0, r1, r2, r3, wd + PL);
                    bl[nh * 2 + 0][0] = r0; bl[nh * 2 + 0][1] = r1;
                    bl[nh * 2 + 1][0] = r2; bl[nh * 2 + 1][1] = r3;
                }
            }
            // ---- A_hi: ldsm interleaved with its HMMAs (LDS/tensor overlap)
            uint32_t a[4][4];
#pragma unroll
            for (int mt = 0; mt < 4; ++mt) {
                uint32_t ad = stg + (uint32_t)(rowA0 + mt * 16) * 64
                            + (uint32_t)(((ks * 2 + cA) ^ sA) << 4);
                ldsm4(a[mt][0], a[mt][1], a[mt][2], a[mt][3], ad);
#pragma unroll
                for (int nt = 0; nt < 4; ++nt) {
                    hmma(acc[mt][nt], a[mt], bh[nt][0], bh[nt][1]);
                    if (PASSES == 3)
                        hmma(acc[mt][nt], a[mt], bl[nt][0], bl[nt][1]);
                }
            }
            // ---- A_lo pass, same interleave ----
#pragma unroll
            for (int mt = 0; mt < 4; ++mt) {
                uint32_t ad = stg + PL + (uint32_t)(rowA0 + mt * 16) * 64
                            + (uint32_t)(((ks * 2 + cA) ^ sA) << 4);
                ldsm4(a[mt][0], a[mt][1], a[mt][2], a[mt][3], ad);
#pragma unroll
                for (int nt = 0; nt < 4; ++nt)
                    hmma(acc[mt][nt], a[mt], bh[nt][0], bh[nt][1]);
            }
        }
    }
#undef ISSUE

    if (FUSED) {
        // ---- fused mlp2: relu(tile) . w2 -> partials [B, 16, 4] ------------
        __syncthreads();                       // pipeline smem now reusable
        float* w2s = (float*)dsm;              // [4][128]
        float* red = (float*)(dsm + 2048);     // [4 warps-n][128 rows][4 outs]
        if (tid < 128) {
#pragma unroll
            for (int o = 0; o < 4; ++o)
                w2s[o * 128 + tid] = w2g[(size_t)o * NFF + blockIdx.x * 128 + tid];
        }
        __syncthreads();

        float po[8][4];
#pragma unroll
        for (int i = 0; i < 8; ++i)
#pragma unroll
            for (int o = 0; o < 4; ++o) po[i][o] = 0.f;

#pragma unroll
        for (int mt = 0; mt < 4; ++mt) {
#pragma unroll
            for (int nt = 0; nt < 4; ++nt) {
                const int clb = wn * 32 + (lane & 3) * 2 + nt * 8;
                const float b0 = bias[blockIdx.x * 128 + clb];
                const float b1v = bias[blockIdx.x * 128 + clb + 1];
                float t00 = fmaxf(acc[mt][nt][0] + b0, 0.f);
                float t01 = fmaxf(acc[mt][nt][1] + b1v, 0.f);
                float t10 = fmaxf(acc[mt][nt][2] + b0, 0.f);
                float t11 = fmaxf(acc[mt][nt][3] + b1v, 0.f);
#pragma unroll
                for (int o = 0; o < 4; ++o) {
                    float w0 = w2s[o * 128 + clb], w1w = w2s[o * 128 + clb + 1];
                    po[mt * 2 + 0][o] += t00 * w0 + t01 * w1w;
                    po[mt * 2 + 1][o] += t10 * w0 + t11 * w1w;
                }
            }
        }
#pragma unroll
        for (int off = 1; off <= 2; off <<= 1)
#pragma unroll
            for (int i = 0; i < 8; ++i)
#pragma unroll
                for (int o = 0; o < 4; ++o)
                    po[i][o] += __shfl_xor_sync(0xffffffffu, po[i][o], off);

        if ((lane & 3) == 0) {
            const int rq = lane >> 2;
#pragma unroll
            for (int i = 0; i < 8; ++i) {
                int row = wm * 64 + rq + (i >> 1) * 16 + (i & 1) * 8;
#pragma unroll
                for (int o = 0; o < 4; ++o)
                    red[(wn * 128 + row) * 4 + o] = po[i][o];
            }
        }
        __syncthreads();
        if (tid < 128) {
            float4 s = make_float4(0.f, 0.f, 0.f, 0.f);
#pragma unroll
            for (int w = 0; w < 4; ++w) {
                float4 v = *(float4*)&red[(w * 128 + tid) * 4];
                s.x += v.x; s.y += v.y; s.z += v.z; s.w += v.w;
            }
            *(float4*)(part + ((size_t)(blockIdx.y * 128 + tid) * 16
                               + blockIdx.x) * 4) = s;
        }
        return;
    }

    // ---- standard epilogue -------------------------------------------------
    const int row0 = blockIdx.y * 128 + wm * 64 + (lane >> 2);
    const int col0 = blockIdx.x * 128 + wn * 32 + (lane & 3) * 2;
#pragma unroll
    for (int mt = 0; mt < 4; ++mt) {
#pragma unroll
        for (int nt = 0; nt < 4; ++nt) {
            const int cI = col0 + nt * 8;
            const float b0 = bias[cI], b1 = bias[cI + 1];
            float2 v0, v1;
            v0.x = acc[mt][nt][0] + b0; v0.y = acc[mt][nt][1] + b1;
            v1.x = acc[mt][nt][2] + b0; v1.y = acc[mt][nt][3] + b1;
            const int r = row0 + mt * 16;
            if (STORE_C) {
                *(float2*)(C + (size_t)r * N + cI)       = v0;
                *(float2*)(C + (size_t)(r + 8) * N + cI) = v1;
            }
            if (WSPLITS) {
                __half h0, l0, h1, l1;
                split1(v0.x, h0, l0); split1(v0.y, h1, l1);
                *(__half2*)(Oh + (size_t)r * N + cI) = __halves2half2(h0, h1);
                *(__half2*)(Ol + (size_t)r * N + cI) = __halves2half2(l0, l1);
                split1(v1.x, h0, l0); split1(v1.y, h1, l1);
                *(__half2*)(Oh + (size_t)(r + 8) * N + cI) = __halves2half2(h0, h1);
                *(__half2*)(Ol + (size_t)(r + 8) * N + cI) = __halves2half2(l0, l1);
                float r0x = fmaxf(v0.x, 0.f), r0y = fmaxf(v0.y, 0.f);
                float r1x = fmaxf(v1.x, 0.f), r1y = fmaxf(v1.y, 0.f);
                split1(r0x, h0, l0); split1(r0y, h1, l1);
                *(__half2*)(Rh + (size_t)r * N + cI) = __halves2half2(h0, h1);
                *(__half2*)(Rl + (size_t)r * N + cI) = __halves2half2(l0, l1);
                split1(r1x, h0, l0); split1(r1y, h1, l1);
                *(__half2*)(Rh + (size_t)(r + 8) * N + cI) = __halves2half2(h0, h1);
                *(__half2*)(Rl + (size_t)(r + 8) * N + cI) = __halves2half2(l0, l1);
            }
        }
    }
}

// ---------------- prep: all weight/state splits + xy zero, ONE launch -------
__global__ void prep_kernel(const float* __restrict__ whh, const float* __restrict__ wfc,
                            const float* __restrict__ w1f, const float* __restrict__ ptf,
                            __half* __restrict__ whh_h, __half* __restrict__ whh_l,
                            __half* __restrict__ wfc_h, __half* __restrict__ wfc_l,
                            __half* __restrict__ w1_h,  __half* __restrict__ w1_l,
                            __half* __restrict__ hp_h,  __half* __restrict__ hp_l,
                            float* __restrict__ xy)
{
    const int n0 = 3 * HH * HH;
    const int n1 = n0 + HH * 2 * HH;
    const int n2 = n1 + NFF * HH;
    const int n3 = n2 + NB * HH;
    const int n4 = n3 + NB * NOUT;
    int i = (blockIdx.x * blockDim.x + threadIdx.x) * 4;
    if (i >= n4) return;
    if (i >= n3) {
        *(float4*)(xy + (i - n3)) = make_float4(0.f, 0.f, 0.f, 0.f);
        return;
    }
    const float* src; __half *hi, *lo; int off;
    if (i < n0)      { src = whh; hi = whh_h; lo = whh_l; off = i; }
    else if (i < n1) { src = wfc; hi = wfc_h; lo = wfc_l; off = i - n0; }
    else if (i < n2) { src = w1f; hi = w1_h;  lo = w1_l;  off = i - n1; }
    else             { src = ptf; hi = hp_h;  lo = hp_l;  off = i - n2; }
    float4 v = *(const float4*)(src + off);
    __half h0, l0, h1, l1, h2, l2, h3, l3;
    split1(v.x, h0, l0); split1(v.y, h1, l1);
    split1(v.z, h2, l2); split1(v.w, h3, l3);
    *(__half2*)(hi + off)     = __halves2half2(h0, h1);
    *(__half2*)(hi + off + 2) = __halves2half2(h2, h3);
    *(__half2*)(lo + off)     = __halves2half2(l0, l1);
    *(__half2*)(lo + off + 2) = __halves2half2(l2, l3);
}

// ---------------- GRU gate fusion (r,z,n order); planes in, planes out ------
__global__ void gru_gates_kernel(const float* __restrict__ gh,
                                 const float* __restrict__ x, int ldx,
                                 const __half* __restrict__ php,  // hprev hi
                                 const __half* __restrict__ plp,  // hprev lo
                                 int ldh,
                                 const float* __restrict__ w_ih,  // [3H,4]
                                 const float* __restrict__ b_ih,  // [3H]
                                 __half* __restrict__ ph,         // out hi plane
                                 __half* __restrict__ pl,         // out lo plane
                                 int ldp)
{
    int j = blockIdx.x * blockDim.x + threadIdx.x;   // 0..H-1
    int b = blockIdx.y;
    float4 xv = *(const float4*)(x + (size_t)b * ldx);

    float ig[3];
#pragma unroll
    for (int g = 0; g < 3; ++g) {
        int rI = g * HH + j;
        float4 w = *(const float4*)(w_ih + (size_t)rI * 4);
        ig[g] = b_ih[rI] + xv.x * w.x + xv.y * w.y + xv.z * w.z + xv.w * w.w;
    }
    const float* ghb = gh + (size_t)b * (3 * HH);
    float gr = ghb[j], gz = ghb[HH + j], gn = ghb[2 * HH + j];
    float r = 1.f / (1.f + expf(-(ig[0] + gr)));
    float z = 1.f / (1.f + expf(-(ig[1] + gz)));
    float n = tanhf(ig[2] + r * gn);
    float hp = __half2float(php[(size_t)b * ldh + j])
             + __half2float(plp[(size_t)b * ldh + j]);
    float h = (1.f - z) * n + z * hp;

    __half hh_, hl_;
    split1(h, hh_, hl_);
    ph[(size_t)b * ldp + j] = hh_;
    pl[(size_t)b * ldp + j] = hl_;
}

// ---------------- finalize: sum partials, update xy, write out --------------
__global__ void finalize_kernel(const float* __restrict__ part,
                                const float* __restrict__ b2,
                                float* __restrict__ xy,
                                float* __restrict__ out, int step)
{
    int b = blockIdx.x * blockDim.x + threadIdx.x;
    if (b >= NB) return;
    const float4* p = (const float4*)(part + (size_t)b * 64);
    float4 s = p[0];
#pragma unroll
    for (int j = 1; j < 16; ++j) {
        float4 v = p[j];
        s.x += v.x; s.y += v.y; s.z += v.z; s.w += v.w;
    }
    float4 cur = *(float4*)(xy + (size_t)b * 4);
    cur.x += s.x + b2[0];
    cur.y += s.y + b2[1];
    cur.z += s.z + b2[2];
    cur.w += s.w + b2[3];
    *(float4*)(xy + (size_t)b * 4) = cur;
    *(float4*)(out + (size_t)b * NHOR * NOUT + step * NOUT) = cur;
}

// ---------------- launch -----------------------------------------------------
extern "C" void kernel_launch(void* const* d_in, const int* in_sizes, int n_in,
                              void* d_out, int out_size)
{
    const float* pv   = (const float*)d_in[0];
    const float* ptf  = (const float*)d_in[1];
    const float* w_ih = (const float*)d_in[2];
    const float* w_hh = (const float*)d_in[3];
    const float* b_ih = (const float*)d_in[4];
    const float* b_hh = (const float*)d_in[5];
    const float* w_fc = (const float*)d_in[6];
    const float* b_fc = (const float*)d_in[7];
    const float* w1   = (const float*)d_in[8];
    const float* b1   = (const float*)d_in[9];
    const float* w2   = (const float*)d_in[10];
    const float* b2   = (const float*)d_in[11];
    float* out = (float*)d_out;

    float *gh, *xy, *part;
    __half *hp_h, *hp_l, *hc_h, *hc_l, *hr_h, *hr_l;
    __half *whh_h, *whh_l, *wfc_h, *wfc_l, *w1_h, *w1_l;
    cudaGetSymbolAddress((void**)&gh, g_gh);
    cudaGetSymbolAddress((void**)&xy, g_xy);
    cudaGetSymbolAddress((void**)&part, g_part);
    cudaGetSymbolAddress((void**)&hp_h, g_hp_h);
    cudaGetSymbolAddress((void**)&hp_l, g_hp_l);
    cudaGetSymbolAddress((void**)&hc_h, g_hc_h);
    cudaGetSymbolAddress((void**)&hc_l, g_hc_l);
    cudaGetSymbolAddress((void**)&hr_h, g_hr_h);
    cudaGetSymbolAddress((void**)&hr_l, g_hr_l);
    cudaGetSymbolAddress((void**)&whh_h, g_whh_h);
    cudaGetSymbolAddress((void**)&whh_l, g_whh_l);
    cudaGetSymbolAddress((void**)&wfc_h, g_wfc_h);
    cudaGetSymbolAddress((void**)&wfc_l, g_wfc_l);
    cudaGetSymbolAddress((void**)&w1_h, g_w1_h);
    cudaGetSymbolAddress((void**)&w1_l, g_w1_l);

    cudaFuncSetAttribute(hgemm<1, 0, 3, 0>, cudaFuncAttributeMaxDynamicSharedMemorySize, SMEM_DYN);
    cudaFuncSetAttribute(hgemm<0, 1, 3, 0>, cudaFuncAttributeMaxDynamicSharedMemorySize, SMEM_DYN);
    cudaFuncSetAttribute(hgemm<0, 0, 2, 1>, cudaFuncAttributeMaxDynamicSharedMemorySize, SMEM_DYN);

    // ---- prep (single launch): split weights + ptf, zero xy ----
    {
        const int n4 = 3 * HH * HH + HH * 2 * HH + NFF * HH + NB * HH + NB * NOUT;
        prep_kernel<<<(n4 / 4 + 255) / 256, 256>>>(
            w_hh, w_fc, w1, ptf,
            whh_h, whh_l, wfc_h, wfc_l, w1_h, w1_l, hp_h, hp_l, xy);
    }

    for (int i = 0; i < NHOR; ++i) {
        // cell 1: gh = hprev @ w_hh^T + b_hh ; h1 = gates(xy, gh, hprev)
        hgemm<1, 0, 3, 0><<<dim3(3 * HH / 128, NB / 128), 256, SMEM_DYN>>>(
            hp_h, hp_l, HH, whh_h, whh_l, HH, b_hh, gh, 3 * HH,
            nullptr, nullptr, nullptr, nullptr, nullptr, nullptr);
        gru_gates_kernel<<<dim3(HH / 256, NB), 256>>>(
            gh, xy, NOUT, hp_h, hp_l, HH, w_ih, b_ih,
            hc_h, hc_l, 2 * HH);

        // cell 2: gh = h1 @ w_hh^T + b_hh ; h2 = gates(pv_i, gh, h1)
        hgemm<1, 0, 3, 0><<<dim3(3 * HH / 128, NB / 128), 256, SMEM_DYN>>>(
            hc_h, hc_l, 2 * HH, whh_h, whh_l, HH, b_hh, gh, 3 * HH,
            nullptr, nullptr, nullptr, nullptr, nullptr, nullptr);
        gru_gates_kernel<<<dim3(HH / 256, NB), 256>>>(
            gh, pv + i * NOUT, NHOR * NOUT, hc_h, hc_l, 2 * HH, w_ih, b_ih,
            hc_h + HH, hc_l + HH, 2 * HH);

        // hx = hcat @ w_fc^T + b_fc ; emit hp planes + relu planes (no fp32 C)
        hgemm<0, 1, 3, 0><<<dim3(HH / 128, NB / 128), 256, SMEM_DYN>>>(
            hc_h, hc_l, 2 * HH, wfc_h, wfc_l, 2 * HH, b_fc, nullptr, HH,
            hp_h, hp_l, hr_h, hr_l, nullptr, nullptr);

        // fused: t = relu(relu(hx) @ w1^T + b1); partials = t-tile . w2
        hgemm<0, 0, 2, 1><<<dim3(NFF / 128, NB / 128), 256, SMEM_DYN>>>(
            hr_h, hr_l, HH, w1_h, w1_l, HH, b1, nullptr, NFF,
            nullptr, nullptr, nullptr, nullptr, w2, part);

        // xy += sum(partials) + b2 ; out[:, i, :] = xy
        finalize_kernel<<<(NB + 255) / 256, 256>>>(part, b2, xy, out, i);
    }
}